// round 3
// baseline (speedup 1.0000x reference)
#include <cuda_runtime.h>
#include <math.h>

#define NN 50000
#define EE 400000
#define BG 16
#define NHEAD 4
#define DH 64
#define HD 256      // NHEAD*DH
#define C2 512      // fused fs|fd columns

// ---------------- device scratch (static globals: no allocation) -------------
__device__ float g_h0[NN * 64];          // 12.8 MB
__device__ float g_c[NN * C2];           // 102.4 MB  (h0 @ W_bot + bias, fused src|dst)
__device__ float g_fsd[NN * C2];         // 102.4 MB  (fs | fd per layer)
__device__ float g_h[2][NN * 64];        // 25.6 MB ping-pong
__device__ float g_Wtop[64 * C2];
__device__ float g_Wbot[64 * C2];
__device__ float g_bias[C2];
__device__ int   g_rowoff[NN + 1];
__device__ int   g_cursor[NN];
__device__ int   g_esrc[EE];
__device__ float g_hg[BG * 64];

// ---------------- small kernels ---------------------------------------------
__global__ void k_zero_rowoff() {
    int i = blockIdx.x * blockDim.x + threadIdx.x;
    if (i <= NN) g_rowoff[i] = 0;
}
__global__ void k_zero_hg() {
    int i = blockIdx.x * blockDim.x + threadIdx.x;
    if (i < BG * 64) g_hg[i] = 0.f;
}

__global__ void k_packW(const float* __restrict__ Ws_, const float* __restrict__ Wd_,
                        const float* __restrict__ bs, const float* __restrict__ bd) {
    int idx = blockIdx.x * blockDim.x + threadIdx.x;
    if (idx >= 64 * C2) return;
    int k = idx >> 9, j = idx & 511;
    float vt, vb;
    if (j < 256) { vt = Ws_[k * 256 + j];        vb = Ws_[(k + 64) * 256 + j]; }
    else         { int jj = j - 256; vt = Wd_[k * 256 + jj]; vb = Wd_[(k + 64) * 256 + jj]; }
    g_Wtop[idx] = vt;
    g_Wbot[idx] = vb;
    if (idx < C2) g_bias[idx] = (idx < 256) ? bs[idx] : bd[idx - 256];
}

// h0 = feat @ W_in + b_in  ([N,16] x [16,64])
__global__ void k_h0(const float* __restrict__ feat, const float* __restrict__ W_in,
                     const float* __restrict__ b_in) {
    int idx = blockIdx.x * blockDim.x + threadIdx.x;
    if (idx >= NN * 64) return;
    int i = idx >> 6, d = idx & 63;
    const float4* f4 = (const float4*)(feat + i * 16);
    float4 f0 = f4[0], f1 = f4[1], f2 = f4[2], f3 = f4[3];
    float s = b_in[d];
    s = fmaf(f0.x, W_in[0 * 64 + d], s);  s = fmaf(f0.y, W_in[1 * 64 + d], s);
    s = fmaf(f0.z, W_in[2 * 64 + d], s);  s = fmaf(f0.w, W_in[3 * 64 + d], s);
    s = fmaf(f1.x, W_in[4 * 64 + d], s);  s = fmaf(f1.y, W_in[5 * 64 + d], s);
    s = fmaf(f1.z, W_in[6 * 64 + d], s);  s = fmaf(f1.w, W_in[7 * 64 + d], s);
    s = fmaf(f2.x, W_in[8 * 64 + d], s);  s = fmaf(f2.y, W_in[9 * 64 + d], s);
    s = fmaf(f2.z, W_in[10 * 64 + d], s); s = fmaf(f2.w, W_in[11 * 64 + d], s);
    s = fmaf(f3.x, W_in[12 * 64 + d], s); s = fmaf(f3.y, W_in[13 * 64 + d], s);
    s = fmaf(f3.z, W_in[14 * 64 + d], s); s = fmaf(f3.w, W_in[15 * 64 + d], s);
    g_h0[idx] = s;
}

// ---------------- CSR build --------------------------------------------------
__global__ void k_hist(const int* __restrict__ dst) {
    int e = blockIdx.x * blockDim.x + threadIdx.x;
    if (e < EE) atomicAdd(&g_rowoff[dst[e] + 1], 1);
}

// single-block inclusive scan over g_rowoff[0..NN]
__global__ void k_scan() {
    __shared__ int wtot[32];
    __shared__ int run_s;
    int t = threadIdx.x, lane = t & 31, wid = t >> 5;
    if (t == 0) run_s = 0;
    __syncthreads();
    for (int base = 0; base < NN + 1; base += 1024) {
        int idx = base + t;
        int x = (idx < NN + 1) ? g_rowoff[idx] : 0;
#pragma unroll
        for (int off = 1; off < 32; off <<= 1) {
            int y = __shfl_up_sync(0xffffffffu, x, off);
            if (lane >= off) x += y;
        }
        if (lane == 31) wtot[wid] = x;
        __syncthreads();
        if (wid == 0) {
            int w = wtot[lane];
#pragma unroll
            for (int off = 1; off < 32; off <<= 1) {
                int y = __shfl_up_sync(0xffffffffu, w, off);
                if (lane >= off) w += y;
            }
            wtot[lane] = w;
        }
        __syncthreads();
        int total = wtot[31];
        int add = run_s + (wid ? wtot[wid - 1] : 0);
        if (idx < NN + 1) g_rowoff[idx] = x + add;
        __syncthreads();
        if (t == 0) run_s += total;
        __syncthreads();
    }
}

__global__ void k_copycur() {
    int i = blockIdx.x * blockDim.x + threadIdx.x;
    if (i < NN) g_cursor[i] = g_rowoff[i];
}
__global__ void k_scatter(const int* __restrict__ src, const int* __restrict__ dst) {
    int e = blockIdx.x * blockDim.x + threadIdx.x;
    if (e < EE) {
        int d = dst[e];
        int p = atomicAdd(&g_cursor[d], 1);
        g_esrc[p] = src[e];
    }
}

// ---------------- GEMM: C[M,512] = A[M,64] @ W[64,512] + add ------------------
// asel: 0 = g_h0, 1 = g_h[0], 2 = g_h[1]
// wsel: 0 = g_Wtop, 1 = g_Wbot
// csel: 0 = g_fsd, 1 = g_c
// addmode: 1 = broadcast g_bias, 0 = elementwise g_c
__global__ void __launch_bounds__(256) k_gemm(int asel, int wsel, int csel, int addmode) {
    __shared__ float As[128 * 64];   // 32 KB, row-major [m][k]
    __shared__ float Ws[64 * 64];    // 16 KB, [k][n]
    const float* A = (asel == 0) ? g_h0 : g_h[asel - 1];
    const float* W = wsel ? g_Wbot : g_Wtop;
    float* C = csel ? g_c : g_fsd;

    int row0 = blockIdx.y * 128;
    int col0 = blockIdx.x * 64;
    int tid = threadIdx.x;

    // load A tile: 128x64 floats = 2048 float4, 8 per thread, coalesced
#pragma unroll
    for (int it = 0; it < 8; it++) {
        int idx = tid + 256 * it;        // 0..2047
        int r = idx >> 4;                // row within tile
        int k4 = idx & 15;               // float4 along K
        int grow = row0 + r;
        float4 v = make_float4(0.f, 0.f, 0.f, 0.f);
        if (grow < NN) v = *(const float4*)(A + grow * 64 + k4 * 4);
        *(float4*)&As[r * 64 + k4 * 4] = v;
    }
    // load W tile: 64x64 floats = 1024 float4, 4 per thread
#pragma unroll
    for (int it = 0; it < 4; it++) {
        int idx = tid + 256 * it;        // 0..1023
        int k = idx >> 4;
        int n4 = idx & 15;
        *(float4*)&Ws[k * 64 + n4 * 4] = *(const float4*)(W + k * C2 + col0 + n4 * 4);
    }
    __syncthreads();

    int tx = tid & 15, ty = tid >> 4;    // 16x16 thread grid; each thread 8 rows x 4 cols
    float acc[8][4];
#pragma unroll
    for (int mi = 0; mi < 8; mi++)
#pragma unroll
        for (int ni = 0; ni < 4; ni++) acc[mi][ni] = 0.f;

#pragma unroll
    for (int kc = 0; kc < 16; kc++) {
        float4 a4[8];
#pragma unroll
        for (int mi = 0; mi < 8; mi++)
            a4[mi] = *(const float4*)&As[(ty * 8 + mi) * 64 + kc * 4];  // warp-broadcast
#pragma unroll
        for (int kk = 0; kk < 4; kk++) {
            float4 w4 = *(const float4*)&Ws[(kc * 4 + kk) * 64 + tx * 4];
#pragma unroll
            for (int mi = 0; mi < 8; mi++) {
                float av = (kk == 0) ? a4[mi].x : (kk == 1) ? a4[mi].y
                          : (kk == 2) ? a4[mi].z : a4[mi].w;
                acc[mi][0] = fmaf(av, w4.x, acc[mi][0]);
                acc[mi][1] = fmaf(av, w4.y, acc[mi][1]);
                acc[mi][2] = fmaf(av, w4.z, acc[mi][2]);
                acc[mi][3] = fmaf(av, w4.w, acc[mi][3]);
            }
        }
    }

    int gc = col0 + tx * 4;
#pragma unroll
    for (int mi = 0; mi < 8; mi++) {
        int grow = row0 + ty * 8 + mi;
        if (grow < NN) {
            float4 addv;
            if (addmode) addv = *(const float4*)&g_bias[gc];
            else         addv = *(const float4*)&g_c[grow * C2 + gc];
            float4 o;
            o.x = acc[mi][0] + addv.x;
            o.y = acc[mi][1] + addv.y;
            o.z = acc[mi][2] + addv.z;
            o.w = acc[mi][3] + addv.w;
            *(float4*)&C[grow * C2 + gc] = o;
        }
    }
}

// ---------------- edge aggregation: one warp per destination node -------------
// lane covers positions p = lane*8+j (j<8); head = p/64 = lane/8 (8-lane groups)
__global__ void __launch_bounds__(256) k_agg(const float* __restrict__ attn, int outsel) {
    int gw = (blockIdx.x * blockDim.x + threadIdx.x) >> 5;
    int lane = threadIdx.x & 31;
    if (gw >= NN) return;

    int base = lane * 8;
    const float* fdrow = g_fsd + gw * C2 + HD;
    float4 fdA = *(const float4*)(fdrow + base);
    float4 fdB = *(const float4*)(fdrow + base + 4);
    float4 atA = *(const float4*)(attn + base);
    float4 atB = *(const float4*)(attn + base + 4);
    float fd[8] = {fdA.x, fdA.y, fdA.z, fdA.w, fdB.x, fdB.y, fdB.z, fdB.w};
    float at[8] = {atA.x, atA.y, atA.z, atA.w, atB.x, atB.y, atB.z, atB.w};

    float m = -1e30f, denom = 0.f;
    float acc[8];
#pragma unroll
    for (int j = 0; j < 8; j++) acc[j] = 0.f;

    int e0 = g_rowoff[gw], e1 = g_rowoff[gw + 1];
    for (int e = e0; e < e1; e++) {
        int s = g_esrc[e];
        const float* fsrow = g_fsd + s * C2;
        float4 fsA = *(const float4*)(fsrow + base);
        float4 fsB = *(const float4*)(fsrow + base + 4);
        float fs[8] = {fsA.x, fsA.y, fsA.z, fsA.w, fsB.x, fsB.y, fsB.z, fsB.w};

        float part = 0.f;
#pragma unroll
        for (int j = 0; j < 8; j++) {
            float v = fs[j] + fd[j];
            v = (v > 0.f) ? v : 0.2f * v;      // LeakyReLU(0.2)
            part = fmaf(v, at[j], part);
        }
        // reduce within 8-lane head group
        part += __shfl_xor_sync(0xffffffffu, part, 1);
        part += __shfl_xor_sync(0xffffffffu, part, 2);
        part += __shfl_xor_sync(0xffffffffu, part, 4);

        float l = part;
        float nm = fmaxf(m, l);
        float sc = __expf(m - nm);
        float p  = __expf(l - nm);
        m = nm;
        denom = fmaf(denom, sc, p);
#pragma unroll
        for (int j = 0; j < 8; j++) acc[j] = fmaf(acc[j], sc, p * fs[j]);
    }

    float inv = (denom > 0.f) ? (1.f / denom) : 0.f;
    float t[8];
#pragma unroll
    for (int j = 0; j < 8; j++) t[j] = tanhf(acc[j] * inv);
    // sum over heads: same d lives at lanes differing in bits 3,4
#pragma unroll
    for (int j = 0; j < 8; j++) {
        t[j] += __shfl_xor_sync(0xffffffffu, t[j], 8);
        t[j] += __shfl_xor_sync(0xffffffffu, t[j], 16);
    }
    if (lane < 8) {
        float* hout = g_h[outsel] + gw * 64 + lane * 8;
#pragma unroll
        for (int j = 0; j < 8; j++) hout[j] = t[j];
    }
}

// ---------------- graph pooling + output head --------------------------------
__global__ void k_pool(const float* __restrict__ is_root, const int* __restrict__ gid) {
    __shared__ float sh[BG * 64];
    int t = threadIdx.x;
    for (int x = t; x < BG * 64; x += 256) sh[x] = 0.f;
    __syncthreads();
    const float* h = g_h[1];
    for (int idx = blockIdx.x * 256 + t; idx < NN * 64; idx += gridDim.x * 256) {
        int i = idx >> 6, d = idx & 63;
        atomicAdd(&sh[(gid[i] << 6) | d], h[idx] * is_root[i]);
    }
    __syncthreads();
    for (int x = t; x < BG * 64; x += 256) atomicAdd(&g_hg[x], sh[x]);
}

__global__ void k_out(const float* __restrict__ W_out, const float* __restrict__ b_out,
                      float* __restrict__ out) {
    int t = threadIdx.x;
    if (t >= BG * 32) return;
    int b = t >> 5, j = t & 31;
    float s = b_out[j];
#pragma unroll
    for (int d = 0; d < 64; d++) s = fmaf(g_hg[b * 64 + d], W_out[d * 32 + j], s);
    out[t] = s;
}

// ---------------- launcher ----------------------------------------------------
extern "C" void kernel_launch(void* const* d_in, const int* in_sizes, int n_in,
                              void* d_out, int out_size) {
    const float* feat    = (const float*)d_in[0];
    const float* is_root = (const float*)d_in[1];
    const int*   src     = (const int*)  d_in[2];
    const int*   dst     = (const int*)  d_in[3];
    const int*   gid     = (const int*)  d_in[4];
    const float* W_in    = (const float*)d_in[5];
    const float* b_in    = (const float*)d_in[6];
    const float* W_src   = (const float*)d_in[7];
    const float* b_src   = (const float*)d_in[8];
    const float* W_dst   = (const float*)d_in[9];
    const float* b_dst   = (const float*)d_in[10];
    const float* attn    = (const float*)d_in[11];
    const float* W_out   = (const float*)d_in[12];
    const float* b_out   = (const float*)d_in[13];
    float* out = (float*)d_out;

    // weight packing + h0
    k_packW<<<(64 * C2 + 255) / 256, 256>>>(W_src, W_dst, b_src, b_dst);
    k_h0<<<(NN * 64 + 255) / 256, 256>>>(feat, W_in, b_in);

    // CSR build (dst-sorted)
    k_zero_rowoff<<<(NN + 1 + 255) / 256, 256>>>();
    k_hist<<<(EE + 255) / 256, 256>>>(dst);
    k_scan<<<1, 1024>>>();
    k_copycur<<<(NN + 255) / 256, 256>>>();
    k_scatter<<<(EE + 255) / 256, 256>>>(src, dst);

    dim3 ggrid(C2 / 64, (NN + 127) / 128);
    // g_c = h0 @ Wbot + bias  (constant across layers)
    k_gemm<<<ggrid, 256>>>(0, 1, 1, 1);

    int insel = 0;   // h0
    int outsel = 0;
    for (int L = 0; L < 4; L++) {
        k_gemm<<<ggrid, 256>>>(insel, 0, 0, 0);                 // fsd = h @ Wtop + g_c
        k_agg<<<(NN * 32 + 255) / 256, 256>>>(attn, outsel);    // h_new = layer(h)
        insel = outsel + 1;
        outsel ^= 1;
    }

    // readout (final h is g_h[1])
    k_zero_hg<<<(BG * 64 + 255) / 256, 256>>>();
    k_pool<<<200, 256>>>(is_root, gid);
    k_out<<<1, 512>>>(W_out, b_out, out);
}

// round 6
// speedup vs baseline: 1.5607x; 1.5607x over previous
#include <cuda_runtime.h>
#include <cuda_bf16.h>
#include <stdint.h>
#include <cstdint>
#include <math.h>

#define NN 50000
#define EE 400000
#define BG 16
#define HD 256      // fs / fd columns
#define PAD 72      // smem row pitch in halves (144B, ldmatrix conflict-free)
#define TILEB (128 * PAD * 2)   // one 128-row tile in bytes (18432)

// ---------------- device scratch (static globals: no allocation) -------------
__device__ __align__(16) float g_h0[NN * 64];
__device__ __align__(16) float g_h[2][NN * 64];
__device__ __align__(16) float g_fs[NN * HD];     // 51.2 MB
__device__ __align__(16) float g_fd[NN * HD];     // 51.2 MB
__device__ __align__(16) __nv_bfloat16 g_Ahi[NN * 64];
__device__ __align__(16) __nv_bfloat16 g_Alo[NN * 64];
__device__ __align__(16) __nv_bfloat16 g_A0hi[NN * 64];
__device__ __align__(16) __nv_bfloat16 g_A0lo[NN * 64];
__device__ __align__(16) __nv_bfloat16 g_Wth[512 * 64];  // Wtop hi  [n][k]
__device__ __align__(16) __nv_bfloat16 g_Wtl[512 * 64];  // Wtop lo
__device__ __align__(16) __nv_bfloat16 g_Wbh[512 * 64];  // Wbot hi
__device__ __align__(16) __nv_bfloat16 g_Wbl[512 * 64];  // Wbot lo
__device__ __align__(16) float g_bias2[512];
__device__ int   g_rowoff[NN + 1];
__device__ int   g_cursor[NN];
__device__ int   g_esrc[EE];
__device__ float g_hg[BG * 64];

// ---------------- mma/ldmatrix helpers ----------------------------------------
__device__ __forceinline__ uint32_t s2u(const void* p) {
    uint32_t a;
    asm("{ .reg .u64 t; cvta.to.shared.u64 t, %1; cvt.u32.u64 %0, t; }"
        : "=r"(a) : "l"(p));
    return a;
}
__device__ __forceinline__ void ldsm_x4(uint32_t& r0, uint32_t& r1, uint32_t& r2,
                                        uint32_t& r3, uint32_t addr) {
    asm volatile("ldmatrix.sync.aligned.m8n8.x4.shared.b16 {%0,%1,%2,%3}, [%4];"
                 : "=r"(r0), "=r"(r1), "=r"(r2), "=r"(r3) : "r"(addr));
}
__device__ __forceinline__ void mma16816(float* d, const uint32_t* a,
                                         uint32_t b0, uint32_t b1) {
    asm volatile(
        "mma.sync.aligned.m16n8k16.row.col.f32.bf16.bf16.f32 "
        "{%0,%1,%2,%3}, {%4,%5,%6,%7}, {%8,%9}, {%0,%1,%2,%3};"
        : "+f"(d[0]), "+f"(d[1]), "+f"(d[2]), "+f"(d[3])
        : "r"(a[0]), "r"(a[1]), "r"(a[2]), "r"(a[3]), "r"(b0), "r"(b1));
}

// ---------------- small kernels ----------------------------------------------
__global__ void k_zero_rowoff() {
    int i = blockIdx.x * blockDim.x + threadIdx.x;
    if (i <= NN) g_rowoff[i] = 0;
}
__global__ void k_zero_hg() {
    int i = blockIdx.x * blockDim.x + threadIdx.x;
    if (i < BG * 64) g_hg[i] = 0.f;
}

// pack + bf16-split weights: tiles [n(512)][k(64)]
__global__ void k_cvtW(const float* __restrict__ Ws, const float* __restrict__ Wd,
                       const float* __restrict__ bs, const float* __restrict__ bd) {
    int idx = blockIdx.x * blockDim.x + threadIdx.x;
    if (idx >= 512 * 64) return;
    int n = idx >> 6, k = idx & 63;
    float wt = (n < 256) ? Ws[k * 256 + n] : Wd[k * 256 + (n - 256)];
    float wb = (n < 256) ? Ws[(k + 64) * 256 + n] : Wd[(k + 64) * 256 + (n - 256)];
    __nv_bfloat16 th = __float2bfloat16(wt);
    __nv_bfloat16 bh = __float2bfloat16(wb);
    g_Wth[idx] = th;  g_Wtl[idx] = __float2bfloat16(wt - __bfloat162float(th));
    g_Wbh[idx] = bh;  g_Wbl[idx] = __float2bfloat16(wb - __bfloat162float(bh));
    if (idx < 512) g_bias2[idx] = (idx < 256) ? bs[idx] : bd[idx - 256];
}

// h0 = feat @ W_in + b_in
__global__ void k_h0(const float* __restrict__ feat, const float* __restrict__ W_in,
                     const float* __restrict__ b_in) {
    int idx = blockIdx.x * blockDim.x + threadIdx.x;
    if (idx >= NN * 64) return;
    int i = idx >> 6, d = idx & 63;
    const float4* f4 = (const float4*)(feat + i * 16);
    float4 f0 = f4[0], f1 = f4[1], f2 = f4[2], f3 = f4[3];
    float s = b_in[d];
    s = fmaf(f0.x, W_in[0 * 64 + d], s);  s = fmaf(f0.y, W_in[1 * 64 + d], s);
    s = fmaf(f0.z, W_in[2 * 64 + d], s);  s = fmaf(f0.w, W_in[3 * 64 + d], s);
    s = fmaf(f1.x, W_in[4 * 64 + d], s);  s = fmaf(f1.y, W_in[5 * 64 + d], s);
    s = fmaf(f1.z, W_in[6 * 64 + d], s);  s = fmaf(f1.w, W_in[7 * 64 + d], s);
    s = fmaf(f2.x, W_in[8 * 64 + d], s);  s = fmaf(f2.y, W_in[9 * 64 + d], s);
    s = fmaf(f2.z, W_in[10 * 64 + d], s); s = fmaf(f2.w, W_in[11 * 64 + d], s);
    s = fmaf(f3.x, W_in[12 * 64 + d], s); s = fmaf(f3.y, W_in[13 * 64 + d], s);
    s = fmaf(f3.z, W_in[14 * 64 + d], s); s = fmaf(f3.w, W_in[15 * 64 + d], s);
    g_h0[idx] = s;
}

// fp32 -> bf16 hi/lo split.  srcsel: 0=g_h0, 1=g_h[0], 2=g_h[1];  dsel: 0=A, 1=A0
__global__ void k_cvtA(int srcsel, int dsel) {
    int idx = blockIdx.x * blockDim.x + threadIdx.x;
    if (idx >= NN * 64) return;
    const float* src = (srcsel == 0) ? g_h0 : g_h[srcsel - 1];
    float v = src[idx];
    __nv_bfloat16 hi = __float2bfloat16(v);
    __nv_bfloat16 lo = __float2bfloat16(v - __bfloat162float(hi));
    if (dsel == 0) { g_Ahi[idx] = hi;  g_Alo[idx] = lo; }
    else           { g_A0hi[idx] = hi; g_A0lo[idx] = lo; }
}

// ---------------- CSR build --------------------------------------------------
__global__ void k_hist(const int* __restrict__ dst) {
    int e = blockIdx.x * blockDim.x + threadIdx.x;
    if (e < EE) atomicAdd(&g_rowoff[dst[e] + 1], 1);
}

__global__ void k_scan() {
    __shared__ int wtot[32];
    __shared__ int run_s;
    int t = threadIdx.x, lane = t & 31, wid = t >> 5;
    if (t == 0) run_s = 0;
    __syncthreads();
    for (int base = 0; base < NN + 1; base += 1024) {
        int idx = base + t;
        int x = (idx < NN + 1) ? g_rowoff[idx] : 0;
#pragma unroll
        for (int off = 1; off < 32; off <<= 1) {
            int y = __shfl_up_sync(0xffffffffu, x, off);
            if (lane >= off) x += y;
        }
        if (lane == 31) wtot[wid] = x;
        __syncthreads();
        if (wid == 0) {
            int w = wtot[lane];
#pragma unroll
            for (int off = 1; off < 32; off <<= 1) {
                int y = __shfl_up_sync(0xffffffffu, w, off);
                if (lane >= off) w += y;
            }
            wtot[lane] = w;
        }
        __syncthreads();
        int total = wtot[31];
        int add = run_s + (wid ? wtot[wid - 1] : 0);
        if (idx < NN + 1) g_rowoff[idx] = x + add;
        __syncthreads();
        if (t == 0) run_s += total;
        __syncthreads();
    }
}

__global__ void k_copycur() {
    int i = blockIdx.x * blockDim.x + threadIdx.x;
    if (i < NN) g_cursor[i] = g_rowoff[i];
}
__global__ void k_scatter(const int* __restrict__ src, const int* __restrict__ dst) {
    int e = blockIdx.x * blockDim.x + threadIdx.x;
    if (e < EE) {
        int d = dst[e];
        int p = atomicAdd(&g_cursor[d], 1);
        g_esrc[p] = src[e];
    }
}

// ---------------- HMMA GEMM ----------------------------------------------------
// out[row0:+128, col0:+128] = h@Wtop + h0@Wbot + bias  via 6 K=64 segments:
//   Ahi*Wth + Ahi*Wtl + Alo*Wth + A0hi*Wbh + A0hi*Wbl + A0lo*Wbh
// grid = (4 col blocks, 391 row blocks), 256 threads (8 warps = 4M x 2N),
// warp tile 32x64, mma.m16n8k16 bf16. Dynamic smem: 4 A tiles + 4 B tiles.
__global__ void __launch_bounds__(256, 1) k_mma() {
    extern __shared__ char sm[];
    const int tid = threadIdx.x;
    const int lane = tid & 31;
    const int wid = tid >> 5;
    const int wm = (wid >> 1) * 32;   // warp M offset in tile
    const int wn = (wid & 1) * 64;    // warp N offset in tile
    const int row0 = blockIdx.y * 128;
    const int col0 = blockIdx.x * 128;

    char* smA = sm;                 // 4 * TILEB
    char* smB = sm + 4 * TILEB;     // 4 * TILEB

    // ---- stage A tiles (4 arrays x 128 rows x 64 halves) ----
    {
        const __nv_bfloat16* asrc[4] = {g_Ahi, g_Alo, g_A0hi, g_A0lo};
#pragma unroll
        for (int a = 0; a < 4; a++) {
            char* dstp = smA + a * TILEB;
            const __nv_bfloat16* s = asrc[a];
#pragma unroll
            for (int it = 0; it < 4; it++) {
                int idx = tid + 256 * it;         // 0..1023 float4s
                int r = idx >> 3, c4 = idx & 7;   // row, float4-col (8 halves)
                int grow = row0 + r;
                float4 v = make_float4(0.f, 0.f, 0.f, 0.f);
                if (grow < NN) v = *(const float4*)(s + (size_t)grow * 64 + c4 * 8);
                *(float4*)(dstp + (r * PAD + c4 * 8) * 2) = v;
            }
        }
        const __nv_bfloat16* bsrc[4] = {g_Wth, g_Wtl, g_Wbh, g_Wbl};
#pragma unroll
        for (int b = 0; b < 4; b++) {
            char* dstp = smB + b * TILEB;
            const __nv_bfloat16* s = bsrc[b];
#pragma unroll
            for (int it = 0; it < 4; it++) {
                int idx = tid + 256 * it;
                int r = idx >> 3, c4 = idx & 7;
                float4 v = *(const float4*)(s + (size_t)(col0 + r) * 64 + c4 * 8);
                *(float4*)(dstp + (r * PAD + c4 * 8) * 2) = v;
            }
        }
    }
    __syncthreads();

    // per-lane ldmatrix row/col offsets
    const int a_lrow = lane & 15;            // 0..15
    const int a_lcol = (lane >> 4) << 3;     // 0 / 8
    const int b_lrow = (lane & 7) + ((lane >> 4) << 3);
    const int b_lcol = lane & 8;             // 0 / 8

    float acc[2][8][4];
#pragma unroll
    for (int mt = 0; mt < 2; mt++)
#pragma unroll
        for (int nt = 0; nt < 8; nt++)
#pragma unroll
            for (int j = 0; j < 4; j++) acc[mt][nt][j] = 0.f;

    const int segA[6] = {0, 0, 1, 2, 2, 3};
    const int segB[6] = {0, 1, 0, 2, 3, 2};
    const uint32_t uA = s2u(smA);
    const uint32_t uB = s2u(smB);

#pragma unroll
    for (int seg = 0; seg < 6; seg++) {
        uint32_t aBase = uA + segA[seg] * TILEB;
        uint32_t bBase = uB + segB[seg] * TILEB;
#pragma unroll
        for (int k16 = 0; k16 < 4; k16++) {
            int k0 = k16 * 16;
            uint32_t af[2][4];
#pragma unroll
            for (int mt = 0; mt < 2; mt++) {
                uint32_t ad = aBase + ((wm + mt * 16 + a_lrow) * PAD + k0 + a_lcol) * 2;
                ldsm_x4(af[mt][0], af[mt][1], af[mt][2], af[mt][3], ad);
            }
            uint32_t bf[4][4];
#pragma unroll
            for (int p = 0; p < 4; p++) {
                uint32_t bd = bBase + ((wn + p * 16 + b_lrow) * PAD + k0 + b_lcol) * 2;
                ldsm_x4(bf[p][0], bf[p][1], bf[p][2], bf[p][3], bd);
            }
#pragma unroll
            for (int mt = 0; mt < 2; mt++)
#pragma unroll
                for (int nt = 0; nt < 8; nt++)
                    mma16816(acc[mt][nt], af[mt],
                             bf[nt >> 1][(nt & 1) * 2], bf[nt >> 1][(nt & 1) * 2 + 1]);
        }
    }

    // ---- epilogue: + bias, write to g_fs (col0<256) or g_fd ----
    float* Cb = (col0 < 256) ? g_fs : g_fd;
    const int cb0 = (col0 < 256) ? col0 : col0 - 256;
#pragma unroll
    for (int nt = 0; nt < 8; nt++) {
        int gcol = col0 + wn + nt * 8 + (lane & 3) * 2;
        float b0 = g_bias2[gcol], b1 = g_bias2[gcol + 1];
        int cc = cb0 + wn + nt * 8 + (lane & 3) * 2;
#pragma unroll
        for (int mt = 0; mt < 2; mt++) {
            int rr = row0 + wm + mt * 16 + (lane >> 2);
            if (rr < NN) {
                float2 v0 = make_float2(acc[mt][nt][0] + b0, acc[mt][nt][1] + b1);
                *(float2*)&Cb[(size_t)rr * HD + cc] = v0;
            }
            if (rr + 8 < NN) {
                float2 v1 = make_float2(acc[mt][nt][2] + b0, acc[mt][nt][3] + b1);
                *(float2*)&Cb[(size_t)(rr + 8) * HD + cc] = v1;
            }
        }
    }
}

// ---------------- edge aggregation: one warp per destination node -------------
__global__ void __launch_bounds__(256) k_agg(const float* __restrict__ attn, int outsel) {
    int gw = (blockIdx.x * blockDim.x + threadIdx.x) >> 5;
    int lane = threadIdx.x & 31;
    if (gw >= NN) return;

    int base = lane * 8;
    const float* fdrow = g_fd + (size_t)gw * HD;
    float4 fdA = *(const float4*)(fdrow + base);
    float4 fdB = *(const float4*)(fdrow + base + 4);
    float4 atA = *(const float4*)(attn + base);
    float4 atB = *(const float4*)(attn + base + 4);
    float fd[8] = {fdA.x, fdA.y, fdA.z, fdA.w, fdB.x, fdB.y, fdB.z, fdB.w};
    float at[8] = {atA.x, atA.y, atA.z, atA.w, atB.x, atB.y, atB.z, atB.w};

    float m = -1e30f, denom = 0.f;
    float acc[8];
#pragma unroll
    for (int j = 0; j < 8; j++) acc[j] = 0.f;

    int e0 = g_rowoff[gw], e1 = g_rowoff[gw + 1];
    for (int e = e0; e < e1; e++) {
        int s = g_esrc[e];
        const float* fsrow = g_fs + (size_t)s * HD;
        float4 fsA = *(const float4*)(fsrow + base);
        float4 fsB = *(const float4*)(fsrow + base + 4);
        float fs[8] = {fsA.x, fsA.y, fsA.z, fsA.w, fsB.x, fsB.y, fsB.z, fsB.w};

        float part = 0.f;
#pragma unroll
        for (int j = 0; j < 8; j++) {
            float v = fs[j] + fd[j];
            v = (v > 0.f) ? v : 0.2f * v;      // LeakyReLU(0.2)
            part = fmaf(v, at[j], part);
        }
        part += __shfl_xor_sync(0xffffffffu, part, 1);
        part += __shfl_xor_sync(0xffffffffu, part, 2);
        part += __shfl_xor_sync(0xffffffffu, part, 4);

        float nm = fmaxf(m, part);
        float sc = __expf(m - nm);
        float p  = __expf(part - nm);
        m = nm;
        denom = fmaf(denom, sc, p);
#pragma unroll
        for (int j = 0; j < 8; j++) acc[j] = fmaf(acc[j], sc, p * fs[j]);
    }

    float inv = (denom > 0.f) ? (1.f / denom) : 0.f;
    float t[8];
#pragma unroll
    for (int j = 0; j < 8; j++) t[j] = tanhf(acc[j] * inv);
#pragma unroll
    for (int j = 0; j < 8; j++) {
        t[j] += __shfl_xor_sync(0xffffffffu, t[j], 8);
        t[j] += __shfl_xor_sync(0xffffffffu, t[j], 16);
    }
    if (lane < 8) {
        float* hout = g_h[outsel] + gw * 64 + lane * 8;
#pragma unroll
        for (int j = 0; j < 8; j++) hout[j] = t[j];
    }
}

// ---------------- graph pooling + output head --------------------------------
__global__ void k_pool(const float* __restrict__ is_root, const int* __restrict__ gid) {
    __shared__ float sh[BG * 64];
    int t = threadIdx.x;
    for (int x = t; x < BG * 64; x += 256) sh[x] = 0.f;
    __syncthreads();
    const float* h = g_h[1];
    for (int idx = blockIdx.x * 256 + t; idx < NN * 64; idx += gridDim.x * 256) {
        int i = idx >> 6, d = idx & 63;
        atomicAdd(&sh[(gid[i] << 6) | d], h[idx] * is_root[i]);
    }
    __syncthreads();
    for (int x = t; x < BG * 64; x += 256) atomicAdd(&g_hg[x], sh[x]);
}

__global__ void k_out(const float* __restrict__ W_out, const float* __restrict__ b_out,
                      float* __restrict__ out) {
    int t = threadIdx.x;
    if (t >= BG * 32) return;
    int b = t >> 5, j = t & 31;
    float s = b_out[j];
#pragma unroll
    for (int d = 0; d < 64; d++) s = fmaf(g_hg[b * 64 + d], W_out[d * 32 + j], s);
    out[t] = s;
}

// ---------------- launcher ----------------------------------------------------
#define SMEM_MMA (8 * TILEB)   // 147456 bytes

extern "C" void kernel_launch(void* const* d_in, const int* in_sizes, int n_in,
                              void* d_out, int out_size) {
    const float* feat    = (const float*)d_in[0];
    const float* is_root = (const float*)d_in[1];
    const int*   src     = (const int*)  d_in[2];
    const int*   dst     = (const int*)  d_in[3];
    const int*   gid     = (const int*)  d_in[4];
    const float* W_in    = (const float*)d_in[5];
    const float* b_in    = (const float*)d_in[6];
    const float* W_src   = (const float*)d_in[7];
    const float* b_src   = (const float*)d_in[8];
    const float* W_dst   = (const float*)d_in[9];
    const float* b_dst   = (const float*)d_in[10];
    const float* attn    = (const float*)d_in[11];
    const float* W_out   = (const float*)d_in[12];
    const float* b_out   = (const float*)d_in[13];
    float* out = (float*)d_out;

    cudaFuncSetAttribute(k_mma, cudaFuncAttributeMaxDynamicSharedMemorySize, SMEM_MMA);

    // weights + h0 + h0 bf16 tiles
    k_cvtW<<<(512 * 64 + 255) / 256, 256>>>(W_src, W_dst, b_src, b_dst);
    k_h0<<<(NN * 64 + 255) / 256, 256>>>(feat, W_in, b_in);
    k_cvtA<<<(NN * 64 + 255) / 256, 256>>>(0, 1);   // h0 -> A0 tiles (constant)

    // CSR build (dst CSR)
    k_zero_rowoff<<<(NN + 1 + 255) / 256, 256>>>();
    k_hist<<<(EE + 255) / 256, 256>>>(dst);
    k_scan<<<1, 1024>>>();
    k_copycur<<<(NN + 255) / 256, 256>>>();
    k_scatter<<<(EE + 255) / 256, 256>>>(src, dst);

    dim3 ggrid(4, (NN + 127) / 128);   // col blocks x row blocks
    int insel = 0;   // h0
    int outsel = 0;
    for (int L = 0; L < 4; L++) {
        k_cvtA<<<(NN * 64 + 255) / 256, 256>>>(insel, 0);   // h -> A tiles
        k_mma<<<ggrid, 256, SMEM_MMA>>>();
        k_agg<<<(NN * 32 + 255) / 256, 256>>>(attn, outsel);
        insel = outsel + 1;
        outsel ^= 1;
    }

    // readout (final h is g_h[1])
    k_zero_hg<<<(BG * 64 + 255) / 256, 256>>>();
    k_pool<<<200, 256>>>(is_root, gid);
    k_out<<<1, 512>>>(W_out, b_out, out);
}

// round 7
// speedup vs baseline: 1.7645x; 1.1306x over previous
#include <cuda_runtime.h>
#include <cuda_bf16.h>
#include <stdint.h>
#include <cstdint>
#include <math.h>

#define NN 50000
#define EE 400000
#define BG 16
#define HD 256      // fs / fd columns

// 16B-chunk XOR swizzle on 128B rows (64 halves): conflict-free ldmatrix
#define SWZ(r, c8) (((r) << 7) | ((((c8) ^ ((r) & 7))) << 4))
#define ATILE 16384                 // one 128x64-half tile, bytes
#define SMEM_A (4 * ATILE)          // 64 KB
#define SMEM_B (4 * ATILE)          // 64 KB per buffer
#define SMEM_TOT (SMEM_A + 2 * SMEM_B)   // 192 KB

// ---------------- device scratch (static globals: no allocation) -------------
__device__ __align__(16) float g_h[2][NN * 64];
__device__ __align__(16) float g_fs[NN * HD];     // 51.2 MB
__device__ __align__(16) float g_fd[NN * HD];     // 51.2 MB
__device__ __align__(16) __nv_bfloat16 g_Ahi[NN * 64];
__device__ __align__(16) __nv_bfloat16 g_Alo[NN * 64];
__device__ __align__(16) __nv_bfloat16 g_A0hi[NN * 64];
__device__ __align__(16) __nv_bfloat16 g_A0lo[NN * 64];
__device__ __align__(16) __nv_bfloat16 g_Wth[512 * 64];  // Wtop hi  [n][k]
__device__ __align__(16) __nv_bfloat16 g_Wtl[512 * 64];  // Wtop lo
__device__ __align__(16) __nv_bfloat16 g_Wbh[512 * 64];  // Wbot hi
__device__ __align__(16) __nv_bfloat16 g_Wbl[512 * 64];  // Wbot lo
__device__ __align__(16) float g_bias2[512];
__device__ int   g_rowoff[NN + 1];
__device__ int   g_cursor[NN];
__device__ int   g_esrc[EE];
__device__ float g_hg[BG * 64];

// ---------------- asm helpers -------------------------------------------------
__device__ __forceinline__ uint32_t s2u(const void* p) {
    uint32_t a;
    asm("{ .reg .u64 t; cvta.to.shared.u64 t, %1; cvt.u32.u64 %0, t; }"
        : "=r"(a) : "l"(p));
    return a;
}
__device__ __forceinline__ void cpa16(uint32_t dst, const void* src) {
    asm volatile("cp.async.cg.shared.global [%0], [%1], 16;" :: "r"(dst), "l"(src));
}
#define CPA_COMMIT() asm volatile("cp.async.commit_group;" ::: "memory")
#define CPA_WAIT0()  asm volatile("cp.async.wait_group 0;" ::: "memory")

__device__ __forceinline__ void ldsm_x4(uint32_t& r0, uint32_t& r1, uint32_t& r2,
                                        uint32_t& r3, uint32_t addr) {
    asm volatile("ldmatrix.sync.aligned.m8n8.x4.shared.b16 {%0,%1,%2,%3}, [%4];"
                 : "=r"(r0), "=r"(r1), "=r"(r2), "=r"(r3) : "r"(addr));
}
__device__ __forceinline__ void mma16816(float* d, const uint32_t* a,
                                         uint32_t b0, uint32_t b1) {
    asm volatile(
        "mma.sync.aligned.m16n8k16.row.col.f32.bf16.bf16.f32 "
        "{%0,%1,%2,%3}, {%4,%5,%6,%7}, {%8,%9}, {%0,%1,%2,%3};"
        : "+f"(d[0]), "+f"(d[1]), "+f"(d[2]), "+f"(d[3])
        : "r"(a[0]), "r"(a[1]), "r"(a[2]), "r"(a[3]), "r"(b0), "r"(b1));
}

// ---------------- small kernels ----------------------------------------------
__global__ void k_zero_rowoff() {
    int i = blockIdx.x * blockDim.x + threadIdx.x;
    if (i <= NN) g_rowoff[i] = 0;
}
__global__ void k_zero_hg() {
    int i = blockIdx.x * blockDim.x + threadIdx.x;
    if (i < BG * 64) g_hg[i] = 0.f;
}

// pack + bf16-split weights: tiles [n(512)][k(64)]
__global__ void k_cvtW(const float* __restrict__ Ws, const float* __restrict__ Wd,
                       const float* __restrict__ bs, const float* __restrict__ bd) {
    int idx = blockIdx.x * blockDim.x + threadIdx.x;
    if (idx >= 512 * 64) return;
    int n = idx >> 6, k = idx & 63;
    float wt = (n < 256) ? Ws[k * 256 + n] : Wd[k * 256 + (n - 256)];
    float wb = (n < 256) ? Ws[(k + 64) * 256 + n] : Wd[(k + 64) * 256 + (n - 256)];
    __nv_bfloat16 th = __float2bfloat16(wt);
    __nv_bfloat16 bh = __float2bfloat16(wb);
    g_Wth[idx] = th;  g_Wtl[idx] = __float2bfloat16(wt - __bfloat162float(th));
    g_Wbh[idx] = bh;  g_Wbl[idx] = __float2bfloat16(wb - __bfloat162float(bh));
    if (idx < 512) g_bias2[idx] = (idx < 256) ? bs[idx] : bd[idx - 256];
}

// h0 = feat @ W_in + b_in -> bf16 hi/lo tiles directly (h0 itself never needed in fp32)
__global__ void k_h0(const float* __restrict__ feat, const float* __restrict__ W_in,
                     const float* __restrict__ b_in) {
    int idx = blockIdx.x * blockDim.x + threadIdx.x;
    if (idx >= NN * 64) return;
    int i = idx >> 6, d = idx & 63;
    const float4* f4 = (const float4*)(feat + i * 16);
    float4 f0 = f4[0], f1 = f4[1], f2 = f4[2], f3 = f4[3];
    float s = b_in[d];
    s = fmaf(f0.x, W_in[0 * 64 + d], s);  s = fmaf(f0.y, W_in[1 * 64 + d], s);
    s = fmaf(f0.z, W_in[2 * 64 + d], s);  s = fmaf(f0.w, W_in[3 * 64 + d], s);
    s = fmaf(f1.x, W_in[4 * 64 + d], s);  s = fmaf(f1.y, W_in[5 * 64 + d], s);
    s = fmaf(f1.z, W_in[6 * 64 + d], s);  s = fmaf(f1.w, W_in[7 * 64 + d], s);
    s = fmaf(f2.x, W_in[8 * 64 + d], s);  s = fmaf(f2.y, W_in[9 * 64 + d], s);
    s = fmaf(f2.z, W_in[10 * 64 + d], s); s = fmaf(f2.w, W_in[11 * 64 + d], s);
    s = fmaf(f3.x, W_in[12 * 64 + d], s); s = fmaf(f3.y, W_in[13 * 64 + d], s);
    s = fmaf(f3.z, W_in[14 * 64 + d], s); s = fmaf(f3.w, W_in[15 * 64 + d], s);
    __nv_bfloat16 hi = __float2bfloat16(s);
    g_A0hi[idx] = hi;
    g_A0lo[idx] = __float2bfloat16(s - __bfloat162float(hi));
}

// ---------------- CSR build --------------------------------------------------
__global__ void k_hist(const int* __restrict__ dst) {
    int e = blockIdx.x * blockDim.x + threadIdx.x;
    if (e < EE) atomicAdd(&g_rowoff[dst[e] + 1], 1);
}

__global__ void k_scan() {
    __shared__ int wtot[32];
    __shared__ int run_s;
    int t = threadIdx.x, lane = t & 31, wid = t >> 5;
    if (t == 0) run_s = 0;
    __syncthreads();
    for (int base = 0; base < NN + 1; base += 1024) {
        int idx = base + t;
        int x = (idx < NN + 1) ? g_rowoff[idx] : 0;
#pragma unroll
        for (int off = 1; off < 32; off <<= 1) {
            int y = __shfl_up_sync(0xffffffffu, x, off);
            if (lane >= off) x += y;
        }
        if (lane == 31) wtot[wid] = x;
        __syncthreads();
        if (wid == 0) {
            int w = wtot[lane];
#pragma unroll
            for (int off = 1; off < 32; off <<= 1) {
                int y = __shfl_up_sync(0xffffffffu, w, off);
                if (lane >= off) w += y;
            }
            wtot[lane] = w;
        }
        __syncthreads();
        int total = wtot[31];
        int add = run_s + (wid ? wtot[wid - 1] : 0);
        if (idx < NN + 1) g_rowoff[idx] = x + add;
        __syncthreads();
        if (t == 0) run_s += total;
        __syncthreads();
    }
}

__global__ void k_copycur() {
    int i = blockIdx.x * blockDim.x + threadIdx.x;
    if (i < NN) g_cursor[i] = g_rowoff[i];
}
__global__ void k_scatter(const int* __restrict__ src, const int* __restrict__ dst) {
    int e = blockIdx.x * blockDim.x + threadIdx.x;
    if (e < EE) {
        int d = dst[e];
        int p = atomicAdd(&g_cursor[d], 1);
        g_esrc[p] = src[e];
    }
}

// ---------------- HMMA GEMM (persistent over N, cp.async double-buffered B) ----
// Per CTA: rows row0..row0+127. Loads 4 A tiles once, loops over 4 col blocks of
// 128, computing 6 K=64 segments (bf16-split of h@Wtop + h0@Wbot) per block.
__global__ void __launch_bounds__(256, 1) k_mma(int asel) {
    extern __shared__ char sm[];
    const int tid = threadIdx.x;
    const int lane = tid & 31;
    const int wid = tid >> 5;
    const int wm = (wid >> 1) * 32;   // warp M offset
    const int wn = (wid & 1) * 64;    // warp N offset
    const int row0 = blockIdx.x * 128;

    const uint32_t uA = s2u(sm);
    const uint32_t uB = uA + SMEM_A;

    // ---- stage A tiles (once) + B block 0 via cp.async ----
    {
        const __nv_bfloat16* asrc[4] = {asel ? g_Ahi : g_A0hi, asel ? g_Alo : g_A0lo,
                                        g_A0hi, g_A0lo};
#pragma unroll
        for (int a = 0; a < 4; a++) {
            const __nv_bfloat16* s = asrc[a];
            uint32_t base = uA + a * ATILE;
#pragma unroll
            for (int it = 0; it < 4; it++) {
                int idx = tid + 256 * it;        // 0..1023
                int r = idx >> 3, c8 = idx & 7;
                int grow = row0 + r;
                if (grow < NN)
                    cpa16(base + SWZ(r, c8), s + (size_t)grow * 64 + c8 * 8);
                else
                    *(float4*)(sm + a * ATILE + SWZ(r, c8)) =
                        make_float4(0.f, 0.f, 0.f, 0.f);
            }
        }
        const __nv_bfloat16* bsrc[4] = {g_Wth, g_Wtl, g_Wbh, g_Wbl};
#pragma unroll
        for (int b = 0; b < 4; b++) {
            const __nv_bfloat16* s = bsrc[b];     // block 0 rows 0..127
            uint32_t base = uB + b * ATILE;
#pragma unroll
            for (int it = 0; it < 4; it++) {
                int idx = tid + 256 * it;
                int r = idx >> 3, c8 = idx & 7;
                cpa16(base + SWZ(r, c8), s + (size_t)r * 64 + c8 * 8);
            }
        }
        CPA_COMMIT();
        CPA_WAIT0();
    }
    __syncthreads();

    const int a_lrow = lane & 15;
    const int a_c8 = lane >> 4;            // chunk offset 0/1
    const int b_lrow = (lane & 7) + ((lane >> 4) << 3);
    const int b_c8 = (lane & 8) >> 3;

    const int segA[6] = {0, 0, 1, 2, 2, 3};
    const int segB[6] = {0, 1, 0, 2, 3, 2};

#pragma unroll
    for (int blk = 0; blk < 4; blk++) {
        const uint32_t bBuf = uB + (blk & 1) * SMEM_B;

        // prefetch next col block of B into the other buffer
        if (blk < 3) {
            const __nv_bfloat16* bsrc[4] = {g_Wth, g_Wtl, g_Wbh, g_Wbl};
            uint32_t nBuf = uB + ((blk + 1) & 1) * SMEM_B;
            int nrow0 = (blk + 1) * 128;
#pragma unroll
            for (int b = 0; b < 4; b++) {
                const __nv_bfloat16* s = bsrc[b] + (size_t)nrow0 * 64;
                uint32_t base = nBuf + b * ATILE;
#pragma unroll
                for (int it = 0; it < 4; it++) {
                    int idx = tid + 256 * it;
                    int r = idx >> 3, c8 = idx & 7;
                    cpa16(base + SWZ(r, c8), s + (size_t)r * 64 + c8 * 8);
                }
            }
            CPA_COMMIT();
        }

        float acc[2][8][4];
#pragma unroll
        for (int mt = 0; mt < 2; mt++)
#pragma unroll
            for (int nt = 0; nt < 8; nt++)
#pragma unroll
                for (int j = 0; j < 4; j++) acc[mt][nt][j] = 0.f;

#pragma unroll
        for (int seg = 0; seg < 6; seg++) {
            uint32_t aBase = uA + segA[seg] * ATILE;
            uint32_t bBase = bBuf + segB[seg] * ATILE;
#pragma unroll
            for (int k16 = 0; k16 < 4; k16++) {
                int kc8 = k16 * 2;
                uint32_t af[2][4];
#pragma unroll
                for (int mt = 0; mt < 2; mt++) {
                    int r = wm + mt * 16 + a_lrow;
                    ldsm_x4(af[mt][0], af[mt][1], af[mt][2], af[mt][3],
                            aBase + SWZ(r, kc8 + a_c8));
                }
                uint32_t bf[4][4];
#pragma unroll
                for (int p = 0; p < 4; p++) {
                    int r = wn + p * 16 + b_lrow;
                    ldsm_x4(bf[p][0], bf[p][1], bf[p][2], bf[p][3],
                            bBase + SWZ(r, kc8 + b_c8));
                }
#pragma unroll
                for (int mt = 0; mt < 2; mt++)
#pragma unroll
                    for (int nt = 0; nt < 8; nt++)
                        mma16816(acc[mt][nt], af[mt],
                                 bf[nt >> 1][(nt & 1) * 2], bf[nt >> 1][(nt & 1) * 2 + 1]);
            }
        }

        // ---- epilogue: + bias, write to g_fs (cols<256) or g_fd ----
        {
            int col0 = blk * 128;
            float* Cb = (col0 < 256) ? g_fs : g_fd;
            const int cb0 = (col0 < 256) ? col0 : col0 - 256;
#pragma unroll
            for (int nt = 0; nt < 8; nt++) {
                int gcol = col0 + wn + nt * 8 + (lane & 3) * 2;
                float b0 = g_bias2[gcol], b1 = g_bias2[gcol + 1];
                int cc = cb0 + wn + nt * 8 + (lane & 3) * 2;
#pragma unroll
                for (int mt = 0; mt < 2; mt++) {
                    int rr = row0 + wm + mt * 16 + (lane >> 2);
                    if (rr < NN)
                        *(float2*)&Cb[(size_t)rr * HD + cc] =
                            make_float2(acc[mt][nt][0] + b0, acc[mt][nt][1] + b1);
                    if (rr + 8 < NN)
                        *(float2*)&Cb[(size_t)(rr + 8) * HD + cc] =
                            make_float2(acc[mt][nt][2] + b0, acc[mt][nt][3] + b1);
                }
            }
        }

        if (blk < 3) {
            CPA_WAIT0();
            __syncthreads();
        }
    }
}

// ---------------- edge aggregation: one warp per destination node -------------
// Also emits bf16 hi/lo split of the new h for the next layer's GEMM.
__global__ void __launch_bounds__(256) k_agg(const float* __restrict__ attn, int outsel) {
    int gw = (blockIdx.x * blockDim.x + threadIdx.x) >> 5;
    int lane = threadIdx.x & 31;
    if (gw >= NN) return;

    int base = lane * 8;
    const float* fdrow = g_fd + (size_t)gw * HD;
    float4 fdA = *(const float4*)(fdrow + base);
    float4 fdB = *(const float4*)(fdrow + base + 4);
    float4 atA = *(const float4*)(attn + base);
    float4 atB = *(const float4*)(attn + base + 4);
    float fd[8] = {fdA.x, fdA.y, fdA.z, fdA.w, fdB.x, fdB.y, fdB.z, fdB.w};
    float at[8] = {atA.x, atA.y, atA.z, atA.w, atB.x, atB.y, atB.z, atB.w};

    float m = -1e30f, denom = 0.f;
    float acc[8];
#pragma unroll
    for (int j = 0; j < 8; j++) acc[j] = 0.f;

    int e0 = g_rowoff[gw], e1 = g_rowoff[gw + 1];
    for (int e = e0; e < e1; e++) {
        int s = g_esrc[e];
        const float* fsrow = g_fs + (size_t)s * HD;
        float4 fsA = *(const float4*)(fsrow + base);
        float4 fsB = *(const float4*)(fsrow + base + 4);
        float fs[8] = {fsA.x, fsA.y, fsA.z, fsA.w, fsB.x, fsB.y, fsB.z, fsB.w};

        float part = 0.f;
#pragma unroll
        for (int j = 0; j < 8; j++) {
            float v = fs[j] + fd[j];
            v = (v > 0.f) ? v : 0.2f * v;      // LeakyReLU(0.2)
            part = fmaf(v, at[j], part);
        }
        part += __shfl_xor_sync(0xffffffffu, part, 1);
        part += __shfl_xor_sync(0xffffffffu, part, 2);
        part += __shfl_xor_sync(0xffffffffu, part, 4);

        float nm = fmaxf(m, part);
        float sc = __expf(m - nm);
        float p  = __expf(part - nm);
        m = nm;
        denom = fmaf(denom, sc, p);
#pragma unroll
        for (int j = 0; j < 8; j++) acc[j] = fmaf(acc[j], sc, p * fs[j]);
    }

    float inv = (denom > 0.f) ? (1.f / denom) : 0.f;
    float t[8];
#pragma unroll
    for (int j = 0; j < 8; j++) t[j] = tanhf(acc[j] * inv);
#pragma unroll
    for (int j = 0; j < 8; j++) {
        t[j] += __shfl_xor_sync(0xffffffffu, t[j], 8);
        t[j] += __shfl_xor_sync(0xffffffffu, t[j], 16);
    }
    if (lane < 8) {
        size_t ofs = (size_t)gw * 64 + lane * 8;
        float* hout = g_h[outsel] + ofs;
        __nv_bfloat16* ah = g_Ahi + ofs;
        __nv_bfloat16* al = g_Alo + ofs;
#pragma unroll
        for (int j = 0; j < 8; j++) {
            hout[j] = t[j];
            __nv_bfloat16 hi = __float2bfloat16(t[j]);
            ah[j] = hi;
            al[j] = __float2bfloat16(t[j] - __bfloat162float(hi));
        }
    }
}

// ---------------- graph pooling + output head --------------------------------
__global__ void k_pool(const float* __restrict__ is_root, const int* __restrict__ gid) {
    __shared__ float sh[BG * 64];
    int t = threadIdx.x;
    for (int x = t; x < BG * 64; x += 256) sh[x] = 0.f;
    __syncthreads();
    const float* h = g_h[1];
    for (int idx = blockIdx.x * 256 + t; idx < NN * 64; idx += gridDim.x * 256) {
        int i = idx >> 6, d = idx & 63;
        atomicAdd(&sh[(gid[i] << 6) | d], h[idx] * is_root[i]);
    }
    __syncthreads();
    for (int x = t; x < BG * 64; x += 256) atomicAdd(&g_hg[x], sh[x]);
}

__global__ void k_out(const float* __restrict__ W_out, const float* __restrict__ b_out,
                      float* __restrict__ out) {
    int t = threadIdx.x;
    if (t >= BG * 32) return;
    int b = t >> 5, j = t & 31;
    float s = b_out[j];
#pragma unroll
    for (int d = 0; d < 64; d++) s = fmaf(g_hg[b * 64 + d], W_out[d * 32 + j], s);
    out[t] = s;
}

// ---------------- launcher ----------------------------------------------------
extern "C" void kernel_launch(void* const* d_in, const int* in_sizes, int n_in,
                              void* d_out, int out_size) {
    const float* feat    = (const float*)d_in[0];
    const float* is_root = (const float*)d_in[1];
    const int*   src     = (const int*)  d_in[2];
    const int*   dst     = (const int*)  d_in[3];
    const int*   gid     = (const int*)  d_in[4];
    const float* W_in    = (const float*)d_in[5];
    const float* b_in    = (const float*)d_in[6];
    const float* W_src   = (const float*)d_in[7];
    const float* b_src   = (const float*)d_in[8];
    const float* W_dst   = (const float*)d_in[9];
    const float* b_dst   = (const float*)d_in[10];
    const float* attn    = (const float*)d_in[11];
    const float* W_out   = (const float*)d_in[12];
    const float* b_out   = (const float*)d_in[13];
    float* out = (float*)d_out;

    cudaFuncSetAttribute(k_mma, cudaFuncAttributeMaxDynamicSharedMemorySize, SMEM_TOT);

    // weights + h0 (emitted directly as bf16 hi/lo tiles)
    k_cvtW<<<(512 * 64 + 255) / 256, 256>>>(W_src, W_dst, b_src, b_dst);
    k_h0<<<(NN * 64 + 255) / 256, 256>>>(feat, W_in, b_in);

    // CSR build (dst CSR)
    k_zero_rowoff<<<(NN + 1 + 255) / 256, 256>>>();
    k_hist<<<(EE + 255) / 256, 256>>>(dst);
    k_scan<<<1, 1024>>>();
    k_copycur<<<(NN + 255) / 256, 256>>>();
    k_scatter<<<(EE + 255) / 256, 256>>>(src, dst);

    const int nrb = (NN + 127) / 128;   // 391 row blocks
    int outsel = 0;
    for (int L = 0; L < 4; L++) {
        k_mma<<<nrb, 256, SMEM_TOT>>>(L == 0 ? 0 : 1);
        k_agg<<<(NN * 32 + 255) / 256, 256>>>(attn, outsel);
        outsel ^= 1;
    }

    // readout (final h is g_h[1])
    k_zero_hg<<<(BG * 64 + 255) / 256, 256>>>();
    k_pool<<<200, 256>>>(is_root, gid);
    k_out<<<1, 512>>>(W_out, b_out, out);
}

// round 8
// speedup vs baseline: 1.7984x; 1.0192x over previous
#include <cuda_runtime.h>
#include <cuda_bf16.h>
#include <cuda_fp16.h>
#include <stdint.h>
#include <cstdint>
#include <math.h>

#define NN 50000
#define EE 400000
#define BG 16
#define HD 256      // fs / fd columns

// 16B-chunk XOR swizzle on 128B rows (64 halves): conflict-free ldmatrix
#define SWZ(r, c8) (((r) << 7) | ((((c8) ^ ((r) & 7))) << 4))
#define ATILE 16384                 // one 128x64-half tile, bytes
#define SMEM_A (4 * ATILE)          // 64 KB
#define SMEM_B (4 * ATILE)          // 64 KB per buffer
#define SMEM_TOT (SMEM_A + 2 * SMEM_B)   // 192 KB

// ---------------- device scratch (static globals: no allocation) -------------
__device__ __align__(16) float g_h[2][NN * 64];
__device__ __align__(16) __half g_fsh[NN * HD];    // 25.6 MB
__device__ __align__(16) __half g_fdh[NN * HD];    // 25.6 MB
__device__ __align__(16) __nv_bfloat16 g_Ahi[NN * 64];
__device__ __align__(16) __nv_bfloat16 g_Alo[NN * 64];
__device__ __align__(16) __nv_bfloat16 g_A0hi[NN * 64];
__device__ __align__(16) __nv_bfloat16 g_A0lo[NN * 64];
__device__ __align__(16) __nv_bfloat16 g_Wth[512 * 64];  // Wtop hi  [n][k]
__device__ __align__(16) __nv_bfloat16 g_Wtl[512 * 64];  // Wtop lo
__device__ __align__(16) __nv_bfloat16 g_Wbh[512 * 64];  // Wbot hi
__device__ __align__(16) __nv_bfloat16 g_Wbl[512 * 64];  // Wbot lo
__device__ __align__(16) float g_bias2[512];
__device__ int   g_rowoff[NN + 1];
__device__ int   g_cursor[NN];
__device__ int   g_esrc[EE];
__device__ float g_hg[BG * 64];

// ---------------- asm helpers -------------------------------------------------
__device__ __forceinline__ uint32_t s2u(const void* p) {
    uint32_t a;
    asm("{ .reg .u64 t; cvta.to.shared.u64 t, %1; cvt.u32.u64 %0, t; }"
        : "=r"(a) : "l"(p));
    return a;
}
__device__ __forceinline__ void cpa16(uint32_t dst, const void* src) {
    asm volatile("cp.async.cg.shared.global [%0], [%1], 16;" :: "r"(dst), "l"(src));
}
#define CPA_COMMIT() asm volatile("cp.async.commit_group;" ::: "memory")
#define CPA_WAIT0()  asm volatile("cp.async.wait_group 0;" ::: "memory")

__device__ __forceinline__ void ldsm_x4(uint32_t& r0, uint32_t& r1, uint32_t& r2,
                                        uint32_t& r3, uint32_t addr) {
    asm volatile("ldmatrix.sync.aligned.m8n8.x4.shared.b16 {%0,%1,%2,%3}, [%4];"
                 : "=r"(r0), "=r"(r1), "=r"(r2), "=r"(r3) : "r"(addr));
}
__device__ __forceinline__ void mma16816(float* d, const uint32_t* a,
                                         uint32_t b0, uint32_t b1) {
    asm volatile(
        "mma.sync.aligned.m16n8k16.row.col.f32.bf16.bf16.f32 "
        "{%0,%1,%2,%3}, {%4,%5,%6,%7}, {%8,%9}, {%0,%1,%2,%3};"
        : "+f"(d[0]), "+f"(d[1]), "+f"(d[2]), "+f"(d[3])
        : "r"(a[0]), "r"(a[1]), "r"(a[2]), "r"(a[3]), "r"(b0), "r"(b1));
}

// ---------------- fused setup kernels -----------------------------------------
// pack + bf16-split weights: tiles [n(512)][k(64)]; also zeroes g_hg
__global__ void k_cvtW(const float* __restrict__ Ws, const float* __restrict__ Wd,
                       const float* __restrict__ bs, const float* __restrict__ bd) {
    int idx = blockIdx.x * blockDim.x + threadIdx.x;
    if (idx >= 512 * 64) return;
    if (idx < BG * 64) g_hg[idx] = 0.f;
    int n = idx >> 6, k = idx & 63;
    float wt = (n < 256) ? Ws[k * 256 + n] : Wd[k * 256 + (n - 256)];
    float wb = (n < 256) ? Ws[(k + 64) * 256 + n] : Wd[(k + 64) * 256 + (n - 256)];
    __nv_bfloat16 th = __float2bfloat16(wt);
    __nv_bfloat16 bh = __float2bfloat16(wb);
    g_Wth[idx] = th;  g_Wtl[idx] = __float2bfloat16(wt - __bfloat162float(th));
    g_Wbh[idx] = bh;  g_Wbl[idx] = __float2bfloat16(wb - __bfloat162float(bh));
    if (idx < 512) g_bias2[idx] = (idx < 256) ? bs[idx] : bd[idx - 256];
}

// h0 = feat @ W_in + b_in -> bf16 hi/lo tiles; also zeroes g_rowoff
__global__ void k_h0(const float* __restrict__ feat, const float* __restrict__ W_in,
                     const float* __restrict__ b_in) {
    int idx = blockIdx.x * blockDim.x + threadIdx.x;
    if (idx >= NN * 64) return;
    if (idx <= NN) g_rowoff[idx] = 0;
    int i = idx >> 6, d = idx & 63;
    const float4* f4 = (const float4*)(feat + i * 16);
    float4 f0 = f4[0], f1 = f4[1], f2 = f4[2], f3 = f4[3];
    float s = b_in[d];
    s = fmaf(f0.x, W_in[0 * 64 + d], s);  s = fmaf(f0.y, W_in[1 * 64 + d], s);
    s = fmaf(f0.z, W_in[2 * 64 + d], s);  s = fmaf(f0.w, W_in[3 * 64 + d], s);
    s = fmaf(f1.x, W_in[4 * 64 + d], s);  s = fmaf(f1.y, W_in[5 * 64 + d], s);
    s = fmaf(f1.z, W_in[6 * 64 + d], s);  s = fmaf(f1.w, W_in[7 * 64 + d], s);
    s = fmaf(f2.x, W_in[8 * 64 + d], s);  s = fmaf(f2.y, W_in[9 * 64 + d], s);
    s = fmaf(f2.z, W_in[10 * 64 + d], s); s = fmaf(f2.w, W_in[11 * 64 + d], s);
    s = fmaf(f3.x, W_in[12 * 64 + d], s); s = fmaf(f3.y, W_in[13 * 64 + d], s);
    s = fmaf(f3.z, W_in[14 * 64 + d], s); s = fmaf(f3.w, W_in[15 * 64 + d], s);
    __nv_bfloat16 hi = __float2bfloat16(s);
    g_A0hi[idx] = hi;
    g_A0lo[idx] = __float2bfloat16(s - __bfloat162float(hi));
}

// ---------------- CSR build --------------------------------------------------
__global__ void k_hist(const int* __restrict__ dst) {
    int e = blockIdx.x * blockDim.x + threadIdx.x;
    if (e < EE) atomicAdd(&g_rowoff[dst[e] + 1], 1);
}

// single-block inclusive scan over g_rowoff[0..NN]; also fills g_cursor
__global__ void k_scan() {
    __shared__ int wtot[32];
    __shared__ int run_s;
    int t = threadIdx.x, lane = t & 31, wid = t >> 5;
    if (t == 0) run_s = 0;
    __syncthreads();
    for (int base = 0; base < NN + 1; base += 1024) {
        int idx = base + t;
        int x = (idx < NN + 1) ? g_rowoff[idx] : 0;
#pragma unroll
        for (int off = 1; off < 32; off <<= 1) {
            int y = __shfl_up_sync(0xffffffffu, x, off);
            if (lane >= off) x += y;
        }
        if (lane == 31) wtot[wid] = x;
        __syncthreads();
        if (wid == 0) {
            int w = wtot[lane];
#pragma unroll
            for (int off = 1; off < 32; off <<= 1) {
                int y = __shfl_up_sync(0xffffffffu, w, off);
                if (lane >= off) w += y;
            }
            wtot[lane] = w;
        }
        __syncthreads();
        int total = wtot[31];
        int add = run_s + (wid ? wtot[wid - 1] : 0);
        if (idx < NN + 1) {
            int v = x + add;
            g_rowoff[idx] = v;
            if (idx < NN) g_cursor[idx] = v;
        }
        __syncthreads();
        if (t == 0) run_s += total;
        __syncthreads();
    }
}

__global__ void k_scatter(const int* __restrict__ src, const int* __restrict__ dst) {
    int e = blockIdx.x * blockDim.x + threadIdx.x;
    if (e < EE) {
        int d = dst[e];
        int p = atomicAdd(&g_cursor[d], 1);
        g_esrc[p] = src[e];
    }
}

// ---------------- HMMA GEMM (persistent over N, cp.async double-buffered B) ----
__global__ void __launch_bounds__(256, 1) k_mma(int asel) {
    extern __shared__ char sm[];
    const int tid = threadIdx.x;
    const int lane = tid & 31;
    const int wid = tid >> 5;
    const int wm = (wid >> 1) * 32;
    const int wn = (wid & 1) * 64;
    const int row0 = blockIdx.x * 128;

    const uint32_t uA = s2u(sm);
    const uint32_t uB = uA + SMEM_A;

    // ---- stage A tiles (once) + B block 0 via cp.async ----
    {
        const __nv_bfloat16* asrc[4] = {asel ? g_Ahi : g_A0hi, asel ? g_Alo : g_A0lo,
                                        g_A0hi, g_A0lo};
#pragma unroll
        for (int a = 0; a < 4; a++) {
            const __nv_bfloat16* s = asrc[a];
            uint32_t base = uA + a * ATILE;
#pragma unroll
            for (int it = 0; it < 4; it++) {
                int idx = tid + 256 * it;
                int r = idx >> 3, c8 = idx & 7;
                int grow = row0 + r;
                if (grow < NN)
                    cpa16(base + SWZ(r, c8), s + (size_t)grow * 64 + c8 * 8);
                else
                    *(float4*)(sm + a * ATILE + SWZ(r, c8)) =
                        make_float4(0.f, 0.f, 0.f, 0.f);
            }
        }
        const __nv_bfloat16* bsrc[4] = {g_Wth, g_Wtl, g_Wbh, g_Wbl};
#pragma unroll
        for (int b = 0; b < 4; b++) {
            const __nv_bfloat16* s = bsrc[b];
            uint32_t base = uB + b * ATILE;
#pragma unroll
            for (int it = 0; it < 4; it++) {
                int idx = tid + 256 * it;
                int r = idx >> 3, c8 = idx & 7;
                cpa16(base + SWZ(r, c8), s + (size_t)r * 64 + c8 * 8);
            }
        }
        CPA_COMMIT();
        CPA_WAIT0();
    }
    __syncthreads();

    const int a_lrow = lane & 15;
    const int a_c8 = lane >> 4;
    const int b_lrow = (lane & 7) + ((lane >> 4) << 3);
    const int b_c8 = (lane & 8) >> 3;

    const int segA[6] = {0, 0, 1, 2, 2, 3};
    const int segB[6] = {0, 1, 0, 2, 3, 2};

#pragma unroll
    for (int blk = 0; blk < 4; blk++) {
        const uint32_t bBuf = uB + (blk & 1) * SMEM_B;

        if (blk < 3) {
            const __nv_bfloat16* bsrc[4] = {g_Wth, g_Wtl, g_Wbh, g_Wbl};
            uint32_t nBuf = uB + ((blk + 1) & 1) * SMEM_B;
            int nrow0 = (blk + 1) * 128;
#pragma unroll
            for (int b = 0; b < 4; b++) {
                const __nv_bfloat16* s = bsrc[b] + (size_t)nrow0 * 64;
                uint32_t base = nBuf + b * ATILE;
#pragma unroll
                for (int it = 0; it < 4; it++) {
                    int idx = tid + 256 * it;
                    int r = idx >> 3, c8 = idx & 7;
                    cpa16(base + SWZ(r, c8), s + (size_t)r * 64 + c8 * 8);
                }
            }
            CPA_COMMIT();
        }

        float acc[2][8][4];
#pragma unroll
        for (int mt = 0; mt < 2; mt++)
#pragma unroll
            for (int nt = 0; nt < 8; nt++)
#pragma unroll
                for (int j = 0; j < 4; j++) acc[mt][nt][j] = 0.f;

#pragma unroll
        for (int seg = 0; seg < 6; seg++) {
            uint32_t aBase = uA + segA[seg] * ATILE;
            uint32_t bBase = bBuf + segB[seg] * ATILE;
#pragma unroll
            for (int k16 = 0; k16 < 4; k16++) {
                int kc8 = k16 * 2;
                uint32_t af[2][4];
#pragma unroll
                for (int mt = 0; mt < 2; mt++) {
                    int r = wm + mt * 16 + a_lrow;
                    ldsm_x4(af[mt][0], af[mt][1], af[mt][2], af[mt][3],
                            aBase + SWZ(r, kc8 + a_c8));
                }
                uint32_t bf[4][4];
#pragma unroll
                for (int p = 0; p < 4; p++) {
                    int r = wn + p * 16 + b_lrow;
                    ldsm_x4(bf[p][0], bf[p][1], bf[p][2], bf[p][3],
                            bBase + SWZ(r, kc8 + b_c8));
                }
#pragma unroll
                for (int mt = 0; mt < 2; mt++)
#pragma unroll
                    for (int nt = 0; nt < 8; nt++)
                        mma16816(acc[mt][nt], af[mt],
                                 bf[nt >> 1][(nt & 1) * 2], bf[nt >> 1][(nt & 1) * 2 + 1]);
            }
        }

        // ---- epilogue: + bias, convert fp16, write fs (cols<256) or fd ----
        {
            int col0 = blk * 128;
            __half* Cb = (col0 < 256) ? g_fsh : g_fdh;
            const int cb0 = (col0 < 256) ? col0 : col0 - 256;
#pragma unroll
            for (int nt = 0; nt < 8; nt++) {
                int gcol = col0 + wn + nt * 8 + (lane & 3) * 2;
                float b0 = g_bias2[gcol], b1 = g_bias2[gcol + 1];
                int cc = cb0 + wn + nt * 8 + (lane & 3) * 2;
#pragma unroll
                for (int mt = 0; mt < 2; mt++) {
                    int rr = row0 + wm + mt * 16 + (lane >> 2);
                    if (rr < NN)
                        *(__half2*)&Cb[(size_t)rr * HD + cc] =
                            __floats2half2_rn(acc[mt][nt][0] + b0, acc[mt][nt][1] + b1);
                    if (rr + 8 < NN)
                        *(__half2*)&Cb[(size_t)(rr + 8) * HD + cc] =
                            __floats2half2_rn(acc[mt][nt][2] + b0, acc[mt][nt][3] + b1);
                }
            }
        }

        if (blk < 3) {
            CPA_WAIT0();
            __syncthreads();
        }
    }
}

// ---------------- edge aggregation: one warp per destination node -------------
__global__ void __launch_bounds__(256) k_agg(const float* __restrict__ attn, int outsel) {
    int gw = (blockIdx.x * blockDim.x + threadIdx.x) >> 5;
    int lane = threadIdx.x & 31;
    if (gw >= NN) return;

    int base = lane * 8;
    float fd[8], at[8];
    {
        uint4 u = *(const uint4*)(g_fdh + (size_t)gw * HD + base);
        const __half2* hp = (const __half2*)&u;
        float2 a = __half22float2(hp[0]), b = __half22float2(hp[1]);
        float2 c = __half22float2(hp[2]), d = __half22float2(hp[3]);
        fd[0] = a.x; fd[1] = a.y; fd[2] = b.x; fd[3] = b.y;
        fd[4] = c.x; fd[5] = c.y; fd[6] = d.x; fd[7] = d.y;
        float4 atA = *(const float4*)(attn + base);
        float4 atB = *(const float4*)(attn + base + 4);
        at[0] = atA.x; at[1] = atA.y; at[2] = atA.z; at[3] = atA.w;
        at[4] = atB.x; at[5] = atB.y; at[6] = atB.z; at[7] = atB.w;
    }

    float m = -1e30f, denom = 0.f;
    float acc[8];
#pragma unroll
    for (int j = 0; j < 8; j++) acc[j] = 0.f;

    int e0 = g_rowoff[gw], e1 = g_rowoff[gw + 1];
    for (int e = e0; e < e1; e++) {
        int s = g_esrc[e];
        uint4 u = *(const uint4*)(g_fsh + (size_t)s * HD + base);
        const __half2* hp = (const __half2*)&u;
        float2 a = __half22float2(hp[0]), b = __half22float2(hp[1]);
        float2 c = __half22float2(hp[2]), d = __half22float2(hp[3]);
        float fs[8] = {a.x, a.y, b.x, b.y, c.x, c.y, d.x, d.y};

        float part = 0.f;
#pragma unroll
        for (int j = 0; j < 8; j++) {
            float v = fs[j] + fd[j];
            v = (v > 0.f) ? v : 0.2f * v;      // LeakyReLU(0.2)
            part = fmaf(v, at[j], part);
        }
        part += __shfl_xor_sync(0xffffffffu, part, 1);
        part += __shfl_xor_sync(0xffffffffu, part, 2);
        part += __shfl_xor_sync(0xffffffffu, part, 4);

        float nm = fmaxf(m, part);
        float sc = __expf(m - nm);
        float p  = __expf(part - nm);
        m = nm;
        denom = fmaf(denom, sc, p);
#pragma unroll
        for (int j = 0; j < 8; j++) acc[j] = fmaf(acc[j], sc, p * fs[j]);
    }

    float inv = (denom > 0.f) ? (1.f / denom) : 0.f;
    float t[8];
#pragma unroll
    for (int j = 0; j < 8; j++) t[j] = tanhf(acc[j] * inv);
#pragma unroll
    for (int j = 0; j < 8; j++) {
        t[j] += __shfl_xor_sync(0xffffffffu, t[j], 8);
        t[j] += __shfl_xor_sync(0xffffffffu, t[j], 16);
    }
    if (lane < 8) {
        size_t ofs = (size_t)gw * 64 + lane * 8;
        float* hout = g_h[outsel] + ofs;
        __nv_bfloat16* ah = g_Ahi + ofs;
        __nv_bfloat16* al = g_Alo + ofs;
#pragma unroll
        for (int j = 0; j < 8; j++) {
            hout[j] = t[j];
            __nv_bfloat16 hi = __float2bfloat16(t[j]);
            ah[j] = hi;
            al[j] = __float2bfloat16(t[j] - __bfloat162float(hi));
        }
    }
}

// ---------------- graph pooling + output head --------------------------------
__global__ void k_pool(const float* __restrict__ is_root, const int* __restrict__ gid) {
    __shared__ float sh[BG * 64];
    int t = threadIdx.x;
    for (int x = t; x < BG * 64; x += 256) sh[x] = 0.f;
    __syncthreads();
    const float* h = g_h[1];
    for (int idx = blockIdx.x * 256 + t; idx < NN * 64; idx += gridDim.x * 256) {
        int i = idx >> 6, d = idx & 63;
        atomicAdd(&sh[(gid[i] << 6) | d], h[idx] * is_root[i]);
    }
    __syncthreads();
    for (int x = t; x < BG * 64; x += 256) atomicAdd(&g_hg[x], sh[x]);
}

__global__ void k_out(const float* __restrict__ W_out, const float* __restrict__ b_out,
                      float* __restrict__ out) {
    int t = threadIdx.x;
    if (t >= BG * 32) return;
    int b = t >> 5, j = t & 31;
    float s = b_out[j];
#pragma unroll
    for (int d = 0; d < 64; d++) s = fmaf(g_hg[b * 64 + d], W_out[d * 32 + j], s);
    out[t] = s;
}

// ---------------- launcher ----------------------------------------------------
extern "C" void kernel_launch(void* const* d_in, const int* in_sizes, int n_in,
                              void* d_out, int out_size) {
    const float* feat    = (const float*)d_in[0];
    const float* is_root = (const float*)d_in[1];
    const int*   src     = (const int*)  d_in[2];
    const int*   dst     = (const int*)  d_in[3];
    const int*   gid     = (const int*)  d_in[4];
    const float* W_in    = (const float*)d_in[5];
    const float* b_in    = (const float*)d_in[6];
    const float* W_src   = (const float*)d_in[7];
    const float* b_src   = (const float*)d_in[8];
    const float* W_dst   = (const float*)d_in[9];
    const float* b_dst   = (const float*)d_in[10];
    const float* attn    = (const float*)d_in[11];
    const float* W_out   = (const float*)d_in[12];
    const float* b_out   = (const float*)d_in[13];
    float* out = (float*)d_out;

    cudaFuncSetAttribute(k_mma, cudaFuncAttributeMaxDynamicSharedMemorySize, SMEM_TOT);

    // 0: weights (+ zero g_hg)    1: h0 tiles (+ zero g_rowoff)
    k_cvtW<<<(512 * 64 + 255) / 256, 256>>>(W_src, W_dst, b_src, b_dst);
    k_h0<<<(NN * 64 + 255) / 256, 256>>>(feat, W_in, b_in);
    // 2-4: CSR build
    k_hist<<<(EE + 255) / 256, 256>>>(dst);
    k_scan<<<1, 1024>>>();
    k_scatter<<<(EE + 255) / 256, 256>>>(src, dst);

    const int nrb = (NN + 127) / 128;   // 391 row blocks
    int outsel = 0;
    for (int L = 0; L < 4; L++) {
        k_mma<<<nrb, 256, SMEM_TOT>>>(L == 0 ? 0 : 1);    // launch 5 = first k_mma
        k_agg<<<(NN * 32 + 255) / 256, 256>>>(attn, outsel);
        outsel ^= 1;
    }

    // readout (final h is g_h[1])
    k_pool<<<200, 256>>>(is_root, gid);
    k_out<<<1, 512>>>(W_out, b_out, out);
}

// round 9
// speedup vs baseline: 1.9915x; 1.1074x over previous
#include <cuda_runtime.h>
#include <cuda_bf16.h>
#include <cuda_fp16.h>
#include <stdint.h>
#include <cstdint>
#include <math.h>

#define NN 50000
#define EE 400000
#define BG 16
#define HD 256      // fs / fd columns
#define NBLK ((NN + 256) / 256)   // 196 scan blocks

// 16B-chunk XOR swizzle on 128B rows (64 halves): conflict-free ldmatrix
#define SWZ(r, c8) (((r) << 7) | ((((c8) ^ ((r) & 7))) << 4))
#define ATILE 16384                 // one 128x64-half tile, bytes
#define SMEM_A (4 * ATILE)          // 64 KB
#define SMEM_B (4 * ATILE)          // 64 KB per buffer
#define SMEM_TOT (SMEM_A + 2 * SMEM_B)   // 192 KB

// ---------------- device scratch (static globals: no allocation) -------------
__device__ __align__(16) float g_hfin[NN * 64];
__device__ __align__(16) __half g_fsh[NN * HD];    // 25.6 MB
__device__ __align__(16) __half g_fdh[NN * HD];    // 25.6 MB
__device__ __align__(16) __nv_bfloat16 g_Ahi[NN * 64];
__device__ __align__(16) __nv_bfloat16 g_Alo[NN * 64];
__device__ __align__(16) __nv_bfloat16 g_A0hi[NN * 64];
__device__ __align__(16) __nv_bfloat16 g_A0lo[NN * 64];
__device__ __align__(16) __nv_bfloat16 g_Wth[512 * 64];  // Wtop hi  [n][k]
__device__ __align__(16) __nv_bfloat16 g_Wtl[512 * 64];  // Wtop lo
__device__ __align__(16) __nv_bfloat16 g_Wbh[512 * 64];  // Wbot hi
__device__ __align__(16) __nv_bfloat16 g_Wbl[512 * 64];  // Wbot lo
__device__ __align__(16) __nv_bfloat16 g_Wch[512 * 64];  // (Wtop+Wbot) hi (layer 0)
__device__ __align__(16) __nv_bfloat16 g_Wcl[512 * 64];  // (Wtop+Wbot) lo
__device__ __align__(16) float g_bias2[512];
__device__ int   g_rowoff[NN + 1];
__device__ int   g_cursor[NN];
__device__ int   g_esrc[EE];
__device__ int   g_bsum[NBLK];
__device__ float g_hg[BG * 64];

// ---------------- asm helpers -------------------------------------------------
__device__ __forceinline__ uint32_t s2u(const void* p) {
    uint32_t a;
    asm("{ .reg .u64 t; cvta.to.shared.u64 t, %1; cvt.u32.u64 %0, t; }"
        : "=r"(a) : "l"(p));
    return a;
}
__device__ __forceinline__ void cpa16(uint32_t dst, const void* src) {
    asm volatile("cp.async.cg.shared.global [%0], [%1], 16;" :: "r"(dst), "l"(src));
}
#define CPA_COMMIT() asm volatile("cp.async.commit_group;" ::: "memory")
#define CPA_WAIT0()  asm volatile("cp.async.wait_group 0;" ::: "memory")

__device__ __forceinline__ void ldsm_x4(uint32_t& r0, uint32_t& r1, uint32_t& r2,
                                        uint32_t& r3, uint32_t addr) {
    asm volatile("ldmatrix.sync.aligned.m8n8.x4.shared.b16 {%0,%1,%2,%3}, [%4];"
                 : "=r"(r0), "=r"(r1), "=r"(r2), "=r"(r3) : "r"(addr));
}
__device__ __forceinline__ void mma16816(float* d, const uint32_t* a,
                                         uint32_t b0, uint32_t b1) {
    asm volatile(
        "mma.sync.aligned.m16n8k16.row.col.f32.bf16.bf16.f32 "
        "{%0,%1,%2,%3}, {%4,%5,%6,%7}, {%8,%9}, {%0,%1,%2,%3};"
        : "+f"(d[0]), "+f"(d[1]), "+f"(d[2]), "+f"(d[3])
        : "r"(a[0]), "r"(a[1]), "r"(a[2]), "r"(a[3]), "r"(b0), "r"(b1));
}

// ---------------- fused setup kernels -----------------------------------------
// weights pack + bf16-split (incl. layer-0 combined W) + zero rowoff + zero hg
__global__ void k_cvtW(const float* __restrict__ Ws, const float* __restrict__ Wd,
                       const float* __restrict__ bs, const float* __restrict__ bd) {
    int idx = blockIdx.x * blockDim.x + threadIdx.x;
    if (idx <= NN) g_rowoff[idx] = 0;
    if (idx < BG * 64) g_hg[idx] = 0.f;
    if (idx >= 512 * 64) return;
    int n = idx >> 6, k = idx & 63;
    float wt = (n < 256) ? Ws[k * 256 + n] : Wd[k * 256 + (n - 256)];
    float wb = (n < 256) ? Ws[(k + 64) * 256 + n] : Wd[(k + 64) * 256 + (n - 256)];
    float wc = wt + wb;
    __nv_bfloat16 th = __float2bfloat16(wt);
    __nv_bfloat16 bh = __float2bfloat16(wb);
    __nv_bfloat16 ch = __float2bfloat16(wc);
    g_Wth[idx] = th;  g_Wtl[idx] = __float2bfloat16(wt - __bfloat162float(th));
    g_Wbh[idx] = bh;  g_Wbl[idx] = __float2bfloat16(wb - __bfloat162float(bh));
    g_Wch[idx] = ch;  g_Wcl[idx] = __float2bfloat16(wc - __bfloat162float(ch));
    if (idx < 512) g_bias2[idx] = (idx < 256) ? bs[idx] : bd[idx - 256];
}

// h0 tiles + degree histogram
__global__ void k_h0(const float* __restrict__ feat, const float* __restrict__ W_in,
                     const float* __restrict__ b_in, const int* __restrict__ dst) {
    int idx = blockIdx.x * blockDim.x + threadIdx.x;
    if (idx >= NN * 64) return;
    if (idx < EE) atomicAdd(&g_rowoff[dst[idx] + 1], 1);
    int i = idx >> 6, d = idx & 63;
    const float4* f4 = (const float4*)(feat + i * 16);
    float4 f0 = f4[0], f1 = f4[1], f2 = f4[2], f3 = f4[3];
    float s = b_in[d];
    s = fmaf(f0.x, W_in[0 * 64 + d], s);  s = fmaf(f0.y, W_in[1 * 64 + d], s);
    s = fmaf(f0.z, W_in[2 * 64 + d], s);  s = fmaf(f0.w, W_in[3 * 64 + d], s);
    s = fmaf(f1.x, W_in[4 * 64 + d], s);  s = fmaf(f1.y, W_in[5 * 64 + d], s);
    s = fmaf(f1.z, W_in[6 * 64 + d], s);  s = fmaf(f1.w, W_in[7 * 64 + d], s);
    s = fmaf(f2.x, W_in[8 * 64 + d], s);  s = fmaf(f2.y, W_in[9 * 64 + d], s);
    s = fmaf(f2.z, W_in[10 * 64 + d], s); s = fmaf(f2.w, W_in[11 * 64 + d], s);
    s = fmaf(f3.x, W_in[12 * 64 + d], s); s = fmaf(f3.y, W_in[13 * 64 + d], s);
    s = fmaf(f3.z, W_in[14 * 64 + d], s); s = fmaf(f3.w, W_in[15 * 64 + d], s);
    __nv_bfloat16 hi = __float2bfloat16(s);
    g_A0hi[idx] = hi;
    g_A0lo[idx] = __float2bfloat16(s - __bfloat162float(hi));
}

// ---------------- parallel CSR scan -------------------------------------------
// scan1: block-local inclusive scan of g_rowoff chunks; block totals -> g_bsum
__global__ void k_scan1() {
    __shared__ int ws[8];
    int b = blockIdx.x, t = threadIdx.x;
    int lane = t & 31, w = t >> 5;
    int idx = b * 256 + t;
    int x = (idx <= NN) ? g_rowoff[idx] : 0;
#pragma unroll
    for (int off = 1; off < 32; off <<= 1) {
        int y = __shfl_up_sync(0xffffffffu, x, off);
        if (lane >= off) x += y;
    }
    if (lane == 31) ws[w] = x;
    __syncthreads();
    if (w == 0 && lane < 8) {
        int v = ws[lane];
#pragma unroll
        for (int off = 1; off < 8; off <<= 1) {
            int y = __shfl_up_sync(0x000000ffu, v, off, 8);
            if (lane >= off) v += y;
        }
        ws[lane] = v;
    }
    __syncthreads();
    int add = w ? ws[w - 1] : 0;
    x += add;
    if (idx <= NN) g_rowoff[idx] = x;
    if (t == 255) g_bsum[b] = x;
}

// scan3: each block sums bsum[0..b-1], applies offset, fills cursor
__global__ void k_scan3() {
    __shared__ int ws[8];
    int b = blockIdx.x, t = threadIdx.x;
    int lane = t & 31, w = t >> 5;
    int v = (t < b && t < NBLK) ? g_bsum[t] : 0;
#pragma unroll
    for (int off = 16; off > 0; off >>= 1)
        v += __shfl_xor_sync(0xffffffffu, v, off);
    if (lane == 0) ws[w] = v;
    __syncthreads();
    if (t == 0) {
        int s = 0;
#pragma unroll
        for (int i = 0; i < 8; i++) s += ws[i];
        ws[0] = s;
    }
    __syncthreads();
    int add = ws[0];
    int idx = b * 256 + t;
    if (idx <= NN) {
        int r = g_rowoff[idx] + add;
        g_rowoff[idx] = r;
        if (idx < NN) g_cursor[idx] = r;
    }
}

__global__ void k_scatter(const int* __restrict__ src, const int* __restrict__ dst) {
    int e = blockIdx.x * blockDim.x + threadIdx.x;
    if (e < EE) {
        int d = dst[e];
        int p = atomicAdd(&g_cursor[d], 1);
        g_esrc[p] = src[e];
    }
}

// ---------------- HMMA GEMM (persistent over N, cp.async double-buffered B) ----
__device__ __forceinline__ void do_seg(uint32_t aBase, uint32_t bBase,
                                       float (&acc)[2][8][4],
                                       int wm, int wn, int a_lrow, int a_c8,
                                       int b_lrow, int b_c8) {
#pragma unroll
    for (int k16 = 0; k16 < 4; k16++) {
        int kc8 = k16 * 2;
        uint32_t af[2][4];
#pragma unroll
        for (int mt = 0; mt < 2; mt++) {
            int r = wm + mt * 16 + a_lrow;
            ldsm_x4(af[mt][0], af[mt][1], af[mt][2], af[mt][3],
                    aBase + SWZ(r, kc8 + a_c8));
        }
        uint32_t bf[4][4];
#pragma unroll
        for (int p = 0; p < 4; p++) {
            int r = wn + p * 16 + b_lrow;
            ldsm_x4(bf[p][0], bf[p][1], bf[p][2], bf[p][3],
                    bBase + SWZ(r, kc8 + b_c8));
        }
#pragma unroll
        for (int mt = 0; mt < 2; mt++)
#pragma unroll
            for (int nt = 0; nt < 8; nt++)
                mma16816(acc[mt][nt], af[mt],
                         bf[nt >> 1][(nt & 1) * 2], bf[nt >> 1][(nt & 1) * 2 + 1]);
    }
}

__global__ void __launch_bounds__(256, 1) k_mma(int asel) {
    extern __shared__ char sm[];
    const int tid = threadIdx.x;
    const int lane = tid & 31;
    const int wid = tid >> 5;
    const int wm = (wid >> 1) * 32;
    const int wn = (wid & 1) * 64;
    const int row0 = blockIdx.x * 128;

    const uint32_t uA = s2u(sm);
    const uint32_t uB = uA + SMEM_A;

    const __nv_bfloat16* asrc[4];
    const __nv_bfloat16* bsrc[4];
    int na, nb;
    if (asel) {
        asrc[0] = g_Ahi;  asrc[1] = g_Alo;  asrc[2] = g_A0hi; asrc[3] = g_A0lo; na = 4;
        bsrc[0] = g_Wth;  bsrc[1] = g_Wtl;  bsrc[2] = g_Wbh;  bsrc[3] = g_Wbl;  nb = 4;
    } else {
        asrc[0] = g_A0hi; asrc[1] = g_A0lo; na = 2;
        bsrc[0] = g_Wch;  bsrc[1] = g_Wcl;  nb = 2;
    }

    // ---- stage A tiles (once) + B block 0 via cp.async ----
    for (int a = 0; a < na; a++) {
        const __nv_bfloat16* s = asrc[a];
        uint32_t base = uA + a * ATILE;
#pragma unroll
        for (int it = 0; it < 4; it++) {
            int idx = tid + 256 * it;
            int r = idx >> 3, c8 = idx & 7;
            int grow = row0 + r;
            if (grow < NN)
                cpa16(base + SWZ(r, c8), s + (size_t)grow * 64 + c8 * 8);
            else
                *(float4*)(sm + a * ATILE + SWZ(r, c8)) = make_float4(0.f, 0.f, 0.f, 0.f);
        }
    }
    for (int b = 0; b < nb; b++) {
        const __nv_bfloat16* s = bsrc[b];
        uint32_t base = uB + b * ATILE;
#pragma unroll
        for (int it = 0; it < 4; it++) {
            int idx = tid + 256 * it;
            int r = idx >> 3, c8 = idx & 7;
            cpa16(base + SWZ(r, c8), s + (size_t)r * 64 + c8 * 8);
        }
    }
    CPA_COMMIT();
    CPA_WAIT0();
    __syncthreads();

    const int a_lrow = lane & 15;
    const int a_c8 = lane >> 4;
    const int b_lrow = (lane & 7) + ((lane >> 4) << 3);
    const int b_c8 = (lane & 8) >> 3;

#pragma unroll
    for (int blk = 0; blk < 4; blk++) {
        const uint32_t bBuf = uB + (blk & 1) * SMEM_B;

        if (blk < 3) {
            uint32_t nBuf = uB + ((blk + 1) & 1) * SMEM_B;
            int nrow0 = (blk + 1) * 128;
            for (int b = 0; b < nb; b++) {
                const __nv_bfloat16* s = bsrc[b] + (size_t)nrow0 * 64;
                uint32_t base = nBuf + b * ATILE;
#pragma unroll
                for (int it = 0; it < 4; it++) {
                    int idx = tid + 256 * it;
                    int r = idx >> 3, c8 = idx & 7;
                    cpa16(base + SWZ(r, c8), s + (size_t)r * 64 + c8 * 8);
                }
            }
            CPA_COMMIT();
        }

        float acc[2][8][4];
#pragma unroll
        for (int mt = 0; mt < 2; mt++)
#pragma unroll
            for (int nt = 0; nt < 8; nt++)
#pragma unroll
                for (int j = 0; j < 4; j++) acc[mt][nt][j] = 0.f;

        if (asel) {
            do_seg(uA + 0 * ATILE, bBuf + 0 * ATILE, acc, wm, wn, a_lrow, a_c8, b_lrow, b_c8);
            do_seg(uA + 0 * ATILE, bBuf + 1 * ATILE, acc, wm, wn, a_lrow, a_c8, b_lrow, b_c8);
            do_seg(uA + 1 * ATILE, bBuf + 0 * ATILE, acc, wm, wn, a_lrow, a_c8, b_lrow, b_c8);
            do_seg(uA + 2 * ATILE, bBuf + 2 * ATILE, acc, wm, wn, a_lrow, a_c8, b_lrow, b_c8);
            do_seg(uA + 2 * ATILE, bBuf + 3 * ATILE, acc, wm, wn, a_lrow, a_c8, b_lrow, b_c8);
            do_seg(uA + 3 * ATILE, bBuf + 2 * ATILE, acc, wm, wn, a_lrow, a_c8, b_lrow, b_c8);
        } else {
            do_seg(uA + 0 * ATILE, bBuf + 0 * ATILE, acc, wm, wn, a_lrow, a_c8, b_lrow, b_c8);
            do_seg(uA + 0 * ATILE, bBuf + 1 * ATILE, acc, wm, wn, a_lrow, a_c8, b_lrow, b_c8);
            do_seg(uA + 1 * ATILE, bBuf + 0 * ATILE, acc, wm, wn, a_lrow, a_c8, b_lrow, b_c8);
        }

        // ---- epilogue: + bias, convert fp16, write fs (cols<256) or fd ----
        {
            int col0 = blk * 128;
            __half* Cb = (col0 < 256) ? g_fsh : g_fdh;
            const int cb0 = (col0 < 256) ? col0 : col0 - 256;
#pragma unroll
            for (int nt = 0; nt < 8; nt++) {
                int gcol = col0 + wn + nt * 8 + (lane & 3) * 2;
                float b0 = g_bias2[gcol], b1 = g_bias2[gcol + 1];
                int cc = cb0 + wn + nt * 8 + (lane & 3) * 2;
#pragma unroll
                for (int mt = 0; mt < 2; mt++) {
                    int rr = row0 + wm + mt * 16 + (lane >> 2);
                    if (rr < NN)
                        *(__half2*)&Cb[(size_t)rr * HD + cc] =
                            __floats2half2_rn(acc[mt][nt][0] + b0, acc[mt][nt][1] + b1);
                    if (rr + 8 < NN)
                        *(__half2*)&Cb[(size_t)(rr + 8) * HD + cc] =
                            __floats2half2_rn(acc[mt][nt][2] + b0, acc[mt][nt][3] + b1);
                }
            }
        }

        if (blk < 3) {
            CPA_WAIT0();
            __syncthreads();
        }
    }
}

// ---------------- edge aggregation: one warp per destination node -------------
__global__ void __launch_bounds__(256) k_agg(const float* __restrict__ attn, int last) {
    int gw = (blockIdx.x * blockDim.x + threadIdx.x) >> 5;
    int lane = threadIdx.x & 31;
    if (gw >= NN) return;

    int base = lane * 8;
    float fd[8], at[8];
    {
        uint4 u = *(const uint4*)(g_fdh + (size_t)gw * HD + base);
        const __half2* hp = (const __half2*)&u;
        float2 a = __half22float2(hp[0]), b = __half22float2(hp[1]);
        float2 c = __half22float2(hp[2]), d = __half22float2(hp[3]);
        fd[0] = a.x; fd[1] = a.y; fd[2] = b.x; fd[3] = b.y;
        fd[4] = c.x; fd[5] = c.y; fd[6] = d.x; fd[7] = d.y;
        float4 atA = *(const float4*)(attn + base);
        float4 atB = *(const float4*)(attn + base + 4);
        at[0] = atA.x; at[1] = atA.y; at[2] = atA.z; at[3] = atA.w;
        at[4] = atB.x; at[5] = atB.y; at[6] = atB.z; at[7] = atB.w;
    }

    float m = -1e30f, denom = 0.f;
    float acc[8];
#pragma unroll
    for (int j = 0; j < 8; j++) acc[j] = 0.f;

    int e0 = g_rowoff[gw], e1 = g_rowoff[gw + 1];
    int deg = e1 - e0;
    uint4 u = make_uint4(0u, 0u, 0u, 0u);
    int s2 = 0;
    if (deg > 0) {
        int s = g_esrc[e0];
        u = *(const uint4*)(g_fsh + (size_t)s * HD + base);
    }
    if (deg > 1) s2 = g_esrc[e0 + 1];

    for (int i = 0; i < deg; i++) {
        uint4 uc = u;
        int s3 = (i + 2 < deg) ? g_esrc[e0 + i + 2] : 0;
        if (i + 1 < deg)
            u = *(const uint4*)(g_fsh + (size_t)s2 * HD + base);
        s2 = s3;

        const __half2* hp = (const __half2*)&uc;
        float2 a = __half22float2(hp[0]), b = __half22float2(hp[1]);
        float2 c = __half22float2(hp[2]), d = __half22float2(hp[3]);
        float fs[8] = {a.x, a.y, b.x, b.y, c.x, c.y, d.x, d.y};

        float part = 0.f;
#pragma unroll
        for (int j = 0; j < 8; j++) {
            float v = fs[j] + fd[j];
            v = (v > 0.f) ? v : 0.2f * v;      // LeakyReLU(0.2)
            part = fmaf(v, at[j], part);
        }
        part += __shfl_xor_sync(0xffffffffu, part, 1);
        part += __shfl_xor_sync(0xffffffffu, part, 2);
        part += __shfl_xor_sync(0xffffffffu, part, 4);

        float nm = fmaxf(m, part);
        float sc = __expf(m - nm);
        float p  = __expf(part - nm);
        m = nm;
        denom = fmaf(denom, sc, p);
#pragma unroll
        for (int j = 0; j < 8; j++) acc[j] = fmaf(acc[j], sc, p * fs[j]);
    }

    float inv = (denom > 0.f) ? (1.f / denom) : 0.f;
    float t[8];
#pragma unroll
    for (int j = 0; j < 8; j++) t[j] = tanhf(acc[j] * inv);
#pragma unroll
    for (int j = 0; j < 8; j++) {
        t[j] += __shfl_xor_sync(0xffffffffu, t[j], 8);
        t[j] += __shfl_xor_sync(0xffffffffu, t[j], 16);
    }
    if (lane < 8) {
        size_t ofs = (size_t)gw * 64 + lane * 8;
        if (last) {
            float* hout = g_hfin + ofs;
#pragma unroll
            for (int j = 0; j < 8; j++) hout[j] = t[j];
        } else {
            __nv_bfloat16* ah = g_Ahi + ofs;
            __nv_bfloat16* al = g_Alo + ofs;
#pragma unroll
            for (int j = 0; j < 8; j++) {
                __nv_bfloat16 hi = __float2bfloat16(t[j]);
                ah[j] = hi;
                al[j] = __float2bfloat16(t[j] - __bfloat162float(hi));
            }
        }
    }
}

// ---------------- graph pooling + output head --------------------------------
__global__ void k_pool(const float* __restrict__ is_root, const int* __restrict__ gid) {
    __shared__ float sh[BG * 64];
    int t = threadIdx.x;
    for (int x = t; x < BG * 64; x += 256) sh[x] = 0.f;
    __syncthreads();
    for (int idx = blockIdx.x * 256 + t; idx < NN * 64; idx += gridDim.x * 256) {
        int i = idx >> 6, d = idx & 63;
        atomicAdd(&sh[(gid[i] << 6) | d], g_hfin[idx] * is_root[i]);
    }
    __syncthreads();
    for (int x = t; x < BG * 64; x += 256) atomicAdd(&g_hg[x], sh[x]);
}

__global__ void k_out(const float* __restrict__ W_out, const float* __restrict__ b_out,
                      float* __restrict__ out) {
    int t = threadIdx.x;
    if (t >= BG * 32) return;
    int b = t >> 5, j = t & 31;
    float s = b_out[j];
#pragma unroll
    for (int d = 0; d < 64; d++) s = fmaf(g_hg[b * 64 + d], W_out[d * 32 + j], s);
    out[t] = s;
}

// ---------------- launcher ----------------------------------------------------
extern "C" void kernel_launch(void* const* d_in, const int* in_sizes, int n_in,
                              void* d_out, int out_size) {
    const float* feat    = (const float*)d_in[0];
    const float* is_root = (const float*)d_in[1];
    const int*   src     = (const int*)  d_in[2];
    const int*   dst     = (const int*)  d_in[3];
    const int*   gid     = (const int*)  d_in[4];
    const float* W_in    = (const float*)d_in[5];
    const float* b_in    = (const float*)d_in[6];
    const float* W_src   = (const float*)d_in[7];
    const float* b_src   = (const float*)d_in[8];
    const float* W_dst   = (const float*)d_in[9];
    const float* b_dst   = (const float*)d_in[10];
    const float* attn    = (const float*)d_in[11];
    const float* W_out   = (const float*)d_in[12];
    const float* b_out   = (const float*)d_in[13];
    float* out = (float*)d_out;

    cudaFuncSetAttribute(k_mma, cudaFuncAttributeMaxDynamicSharedMemorySize, SMEM_TOT);

    // 0: weights + zero rowoff/hg    1: h0 tiles + hist
    k_cvtW<<<NBLK, 256>>>(W_src, W_dst, b_src, b_dst);
    k_h0<<<(NN * 64 + 255) / 256, 256>>>(feat, W_in, b_in, dst);
    // 2-4: CSR scan + scatter
    k_scan1<<<NBLK, 256>>>();
    k_scan3<<<NBLK, 256>>>();
    k_scatter<<<(EE + 255) / 256, 256>>>(src, dst);

    const int nrb = (NN + 127) / 128;   // 391 row blocks
    for (int L = 0; L < 4; L++) {
        k_mma<<<nrb, 256, SMEM_TOT>>>(L == 0 ? 0 : 1);   // launch 5 = first k_mma
        k_agg<<<(NN * 32 + 255) / 256, 256>>>(attn, L == 3 ? 1 : 0);
    }

    // readout
    k_pool<<<200, 256>>>(is_root, gid);
    k_out<<<1, 512>>>(W_out, b_out, out);
}

// round 10
// speedup vs baseline: 1.9997x; 1.0041x over previous
#include <cuda_runtime.h>
#include <cuda_bf16.h>
#include <cuda_fp16.h>
#include <stdint.h>
#include <cstdint>
#include <math.h>

#define NN 50000
#define EE 400000
#define BG 16
#define HD 256      // fs / fd columns
#define NBLK ((NN + 256) / 256)   // 196 scan blocks

// 16B-chunk XOR swizzle on 128B rows (64 halves): conflict-free ldmatrix
#define SWZ(r, c8) (((r) << 7) | ((((c8) ^ ((r) & 7))) << 4))
#define ATILE 16384                 // one 128x64-half tile, bytes
#define SMEM_A (4 * ATILE)          // 64 KB
#define SMEM_B (4 * ATILE)          // 64 KB per buffer
#define SMEM_TOT (SMEM_A + 2 * SMEM_B)   // 192 KB

// ---------------- device scratch (static globals: no allocation) -------------
__device__ __align__(16) float g_hfin[NN * 64];
__device__ __align__(16) __half g_fsh[NN * HD];    // 25.6 MB
__device__ __align__(16) __half g_fdh[NN * HD];    // 25.6 MB
__device__ __align__(16) __nv_bfloat16 g_Ahi[NN * 64];
__device__ __align__(16) __nv_bfloat16 g_Alo[NN * 64];
__device__ __align__(16) __nv_bfloat16 g_A0hi[NN * 64];
__device__ __align__(16) __nv_bfloat16 g_A0lo[NN * 64];
__device__ __align__(16) __nv_bfloat16 g_Wth[512 * 64];  // Wtop hi  [n][k]
__device__ __align__(16) __nv_bfloat16 g_Wtl[512 * 64];  // Wtop lo
__device__ __align__(16) __nv_bfloat16 g_Wbh[512 * 64];  // Wbot hi
__device__ __align__(16) __nv_bfloat16 g_Wbl[512 * 64];  // Wbot lo
__device__ __align__(16) __nv_bfloat16 g_Wch[512 * 64];  // (Wtop+Wbot) hi (layer 0)
__device__ __align__(16) __nv_bfloat16 g_Wcl[512 * 64];  // (Wtop+Wbot) lo
__device__ __align__(16) float g_bias2[512];
__device__ int   g_rowoff[NN + 1];
__device__ int   g_cursor[NN];
__device__ int   g_esrc[EE];
__device__ int   g_bsum[NBLK];
__device__ float g_hg[BG * 64];

// ---------------- asm helpers -------------------------------------------------
__device__ __forceinline__ uint32_t s2u(const void* p) {
    uint32_t a;
    asm("{ .reg .u64 t; cvta.to.shared.u64 t, %1; cvt.u32.u64 %0, t; }"
        : "=r"(a) : "l"(p));
    return a;
}
__device__ __forceinline__ void cpa16(uint32_t dst, const void* src) {
    asm volatile("cp.async.cg.shared.global [%0], [%1], 16;" :: "r"(dst), "l"(src));
}
#define CPA_COMMIT() asm volatile("cp.async.commit_group;" ::: "memory")
#define CPA_WAIT0()  asm volatile("cp.async.wait_group 0;" ::: "memory")

__device__ __forceinline__ void ldsm_x4(uint32_t& r0, uint32_t& r1, uint32_t& r2,
                                        uint32_t& r3, uint32_t addr) {
    asm volatile("ldmatrix.sync.aligned.m8n8.x4.shared.b16 {%0,%1,%2,%3}, [%4];"
                 : "=r"(r0), "=r"(r1), "=r"(r2), "=r"(r3) : "r"(addr));
}
__device__ __forceinline__ void mma16816(float* d, const uint32_t* a,
                                         uint32_t b0, uint32_t b1) {
    asm volatile(
        "mma.sync.aligned.m16n8k16.row.col.f32.bf16.bf16.f32 "
        "{%0,%1,%2,%3}, {%4,%5,%6,%7}, {%8,%9}, {%0,%1,%2,%3};"
        : "+f"(d[0]), "+f"(d[1]), "+f"(d[2]), "+f"(d[3])
        : "r"(a[0]), "r"(a[1]), "r"(a[2]), "r"(a[3]), "r"(b0), "r"(b1));
}

__device__ __forceinline__ void unp8(const uint4& u, float* f) {
    const __half2* hp = (const __half2*)&u;
    float2 a = __half22float2(hp[0]), b = __half22float2(hp[1]);
    float2 c = __half22float2(hp[2]), d = __half22float2(hp[3]);
    f[0] = a.x; f[1] = a.y; f[2] = b.x; f[3] = b.y;
    f[4] = c.x; f[5] = c.y; f[6] = d.x; f[7] = d.y;
}

// ---------------- fused setup kernels -----------------------------------------
__global__ void k_cvtW(const float* __restrict__ Ws, const float* __restrict__ Wd,
                       const float* __restrict__ bs, const float* __restrict__ bd) {
    int idx = blockIdx.x * blockDim.x + threadIdx.x;
    if (idx <= NN) g_rowoff[idx] = 0;
    if (idx < BG * 64) g_hg[idx] = 0.f;
    if (idx >= 512 * 64) return;
    int n = idx >> 6, k = idx & 63;
    float wt = (n < 256) ? Ws[k * 256 + n] : Wd[k * 256 + (n - 256)];
    float wb = (n < 256) ? Ws[(k + 64) * 256 + n] : Wd[(k + 64) * 256 + (n - 256)];
    float wc = wt + wb;
    __nv_bfloat16 th = __float2bfloat16(wt);
    __nv_bfloat16 bh = __float2bfloat16(wb);
    __nv_bfloat16 ch = __float2bfloat16(wc);
    g_Wth[idx] = th;  g_Wtl[idx] = __float2bfloat16(wt - __bfloat162float(th));
    g_Wbh[idx] = bh;  g_Wbl[idx] = __float2bfloat16(wb - __bfloat162float(bh));
    g_Wch[idx] = ch;  g_Wcl[idx] = __float2bfloat16(wc - __bfloat162float(ch));
    if (idx < 512) g_bias2[idx] = (idx < 256) ? bs[idx] : bd[idx - 256];
}

__global__ void k_h0(const float* __restrict__ feat, const float* __restrict__ W_in,
                     const float* __restrict__ b_in, const int* __restrict__ dst) {
    int idx = blockIdx.x * blockDim.x + threadIdx.x;
    if (idx >= NN * 64) return;
    if (idx < EE) atomicAdd(&g_rowoff[dst[idx] + 1], 1);
    int i = idx >> 6, d = idx & 63;
    const float4* f4 = (const float4*)(feat + i * 16);
    float4 f0 = f4[0], f1 = f4[1], f2 = f4[2], f3 = f4[3];
    float s = b_in[d];
    s = fmaf(f0.x, W_in[0 * 64 + d], s);  s = fmaf(f0.y, W_in[1 * 64 + d], s);
    s = fmaf(f0.z, W_in[2 * 64 + d], s);  s = fmaf(f0.w, W_in[3 * 64 + d], s);
    s = fmaf(f1.x, W_in[4 * 64 + d], s);  s = fmaf(f1.y, W_in[5 * 64 + d], s);
    s = fmaf(f1.z, W_in[6 * 64 + d], s);  s = fmaf(f1.w, W_in[7 * 64 + d], s);
    s = fmaf(f2.x, W_in[8 * 64 + d], s);  s = fmaf(f2.y, W_in[9 * 64 + d], s);
    s = fmaf(f2.z, W_in[10 * 64 + d], s); s = fmaf(f2.w, W_in[11 * 64 + d], s);
    s = fmaf(f3.x, W_in[12 * 64 + d], s); s = fmaf(f3.y, W_in[13 * 64 + d], s);
    s = fmaf(f3.z, W_in[14 * 64 + d], s); s = fmaf(f3.w, W_in[15 * 64 + d], s);
    __nv_bfloat16 hi = __float2bfloat16(s);
    g_A0hi[idx] = hi;
    g_A0lo[idx] = __float2bfloat16(s - __bfloat162float(hi));
}

// ---------------- parallel CSR scan -------------------------------------------
__global__ void k_scan1() {
    __shared__ int ws[8];
    int b = blockIdx.x, t = threadIdx.x;
    int lane = t & 31, w = t >> 5;
    int idx = b * 256 + t;
    int x = (idx <= NN) ? g_rowoff[idx] : 0;
#pragma unroll
    for (int off = 1; off < 32; off <<= 1) {
        int y = __shfl_up_sync(0xffffffffu, x, off);
        if (lane >= off) x += y;
    }
    if (lane == 31) ws[w] = x;
    __syncthreads();
    if (w == 0 && lane < 8) {
        int v = ws[lane];
#pragma unroll
        for (int off = 1; off < 8; off <<= 1) {
            int y = __shfl_up_sync(0x000000ffu, v, off, 8);
            if (lane >= off) v += y;
        }
        ws[lane] = v;
    }
    __syncthreads();
    int add = w ? ws[w - 1] : 0;
    x += add;
    if (idx <= NN) g_rowoff[idx] = x;
    if (t == 255) g_bsum[b] = x;
}

__global__ void k_scan3() {
    __shared__ int ws[8];
    int b = blockIdx.x, t = threadIdx.x;
    int lane = t & 31, w = t >> 5;
    int v = (t < b && t < NBLK) ? g_bsum[t] : 0;
#pragma unroll
    for (int off = 16; off > 0; off >>= 1)
        v += __shfl_xor_sync(0xffffffffu, v, off);
    if (lane == 0) ws[w] = v;
    __syncthreads();
    if (t == 0) {
        int s = 0;
#pragma unroll
        for (int i = 0; i < 8; i++) s += ws[i];
        ws[0] = s;
    }
    __syncthreads();
    int add = ws[0];
    int idx = b * 256 + t;
    if (idx <= NN) {
        int r = g_rowoff[idx] + add;
        g_rowoff[idx] = r;
        if (idx < NN) g_cursor[idx] = r;
    }
}

__global__ void k_scatter(const int* __restrict__ src, const int* __restrict__ dst) {
    int e = blockIdx.x * blockDim.x + threadIdx.x;
    if (e < EE) {
        int d = dst[e];
        int p = atomicAdd(&g_cursor[d], 1);
        g_esrc[p] = src[e];
    }
}

// ---------------- HMMA GEMM (persistent over N, cp.async double-buffered B) ----
// One W-group (3 bf16-split segments) with fragments loaded once per k16:
// acc += Ahi*WH + Ahi*WL + Alo*WH
__device__ __forceinline__ void do_grp(uint32_t aH, uint32_t aL,
                                       uint32_t bH, uint32_t bL,
                                       float (&acc)[2][8][4],
                                       int wm, int wn, int a_lrow, int a_c8,
                                       int b_lrow, int b_c8) {
#pragma unroll
    for (int k16 = 0; k16 < 4; k16++) {
        int kc8 = k16 * 2;
        uint32_t afH[2][4], afL[2][4];
#pragma unroll
        for (int mt = 0; mt < 2; mt++) {
            int r = wm + mt * 16 + a_lrow;
            ldsm_x4(afH[mt][0], afH[mt][1], afH[mt][2], afH[mt][3],
                    aH + SWZ(r, kc8 + a_c8));
            ldsm_x4(afL[mt][0], afL[mt][1], afL[mt][2], afL[mt][3],
                    aL + SWZ(r, kc8 + a_c8));
        }
        uint32_t bfH[4][4], bfL[4][4];
#pragma unroll
        for (int p = 0; p < 4; p++) {
            int r = wn + p * 16 + b_lrow;
            ldsm_x4(bfH[p][0], bfH[p][1], bfH[p][2], bfH[p][3],
                    bH + SWZ(r, kc8 + b_c8));
            ldsm_x4(bfL[p][0], bfL[p][1], bfL[p][2], bfL[p][3],
                    bL + SWZ(r, kc8 + b_c8));
        }
#pragma unroll
        for (int mt = 0; mt < 2; mt++)
#pragma unroll
            for (int nt = 0; nt < 8; nt++) {
                uint32_t h0 = bfH[nt >> 1][(nt & 1) * 2], h1 = bfH[nt >> 1][(nt & 1) * 2 + 1];
                uint32_t l0 = bfL[nt >> 1][(nt & 1) * 2], l1 = bfL[nt >> 1][(nt & 1) * 2 + 1];
                mma16816(acc[mt][nt], afH[mt], h0, h1);
                mma16816(acc[mt][nt], afH[mt], l0, l1);
                mma16816(acc[mt][nt], afL[mt], h0, h1);
            }
    }
}

__global__ void __launch_bounds__(256, 1) k_mma(int asel) {
    extern __shared__ char sm[];
    const int tid = threadIdx.x;
    const int lane = tid & 31;
    const int wid = tid >> 5;
    const int wm = (wid >> 1) * 32;
    const int wn = (wid & 1) * 64;
    const int row0 = blockIdx.x * 128;

    const uint32_t uA = s2u(sm);
    const uint32_t uB = uA + SMEM_A;

    const __nv_bfloat16* asrc[4];
    const __nv_bfloat16* bsrc[4];
    int na, nb;
    if (asel) {
        asrc[0] = g_Ahi;  asrc[1] = g_Alo;  asrc[2] = g_A0hi; asrc[3] = g_A0lo; na = 4;
        bsrc[0] = g_Wth;  bsrc[1] = g_Wtl;  bsrc[2] = g_Wbh;  bsrc[3] = g_Wbl;  nb = 4;
    } else {
        asrc[0] = g_A0hi; asrc[1] = g_A0lo; na = 2;
        bsrc[0] = g_Wch;  bsrc[1] = g_Wcl;  nb = 2;
    }

    for (int a = 0; a < na; a++) {
        const __nv_bfloat16* s = asrc[a];
        uint32_t base = uA + a * ATILE;
#pragma unroll
        for (int it = 0; it < 4; it++) {
            int idx = tid + 256 * it;
            int r = idx >> 3, c8 = idx & 7;
            int grow = row0 + r;
            if (grow < NN)
                cpa16(base + SWZ(r, c8), s + (size_t)grow * 64 + c8 * 8);
            else
                *(float4*)(sm + a * ATILE + SWZ(r, c8)) = make_float4(0.f, 0.f, 0.f, 0.f);
        }
    }
    for (int b = 0; b < nb; b++) {
        const __nv_bfloat16* s = bsrc[b];
        uint32_t base = uB + b * ATILE;
#pragma unroll
        for (int it = 0; it < 4; it++) {
            int idx = tid + 256 * it;
            int r = idx >> 3, c8 = idx & 7;
            cpa16(base + SWZ(r, c8), s + (size_t)r * 64 + c8 * 8);
        }
    }
    CPA_COMMIT();
    CPA_WAIT0();
    __syncthreads();

    const int a_lrow = lane & 15;
    const int a_c8 = lane >> 4;
    const int b_lrow = (lane & 7) + ((lane >> 4) << 3);
    const int b_c8 = (lane & 8) >> 3;

#pragma unroll
    for (int blk = 0; blk < 4; blk++) {
        const uint32_t bBuf = uB + (blk & 1) * SMEM_B;

        if (blk < 3) {
            uint32_t nBuf = uB + ((blk + 1) & 1) * SMEM_B;
            int nrow0 = (blk + 1) * 128;
            for (int b = 0; b < nb; b++) {
                const __nv_bfloat16* s = bsrc[b] + (size_t)nrow0 * 64;
                uint32_t base = nBuf + b * ATILE;
#pragma unroll
                for (int it = 0; it < 4; it++) {
                    int idx = tid + 256 * it;
                    int r = idx >> 3, c8 = idx & 7;
                    cpa16(base + SWZ(r, c8), s + (size_t)r * 64 + c8 * 8);
                }
            }
            CPA_COMMIT();
        }

        float acc[2][8][4];
#pragma unroll
        for (int mt = 0; mt < 2; mt++)
#pragma unroll
            for (int nt = 0; nt < 8; nt++)
#pragma unroll
                for (int j = 0; j < 4; j++) acc[mt][nt][j] = 0.f;

        if (asel) {
            do_grp(uA + 0 * ATILE, uA + 1 * ATILE, bBuf + 0 * ATILE, bBuf + 1 * ATILE,
                   acc, wm, wn, a_lrow, a_c8, b_lrow, b_c8);
            do_grp(uA + 2 * ATILE, uA + 3 * ATILE, bBuf + 2 * ATILE, bBuf + 3 * ATILE,
                   acc, wm, wn, a_lrow, a_c8, b_lrow, b_c8);
        } else {
            do_grp(uA + 0 * ATILE, uA + 1 * ATILE, bBuf + 0 * ATILE, bBuf + 1 * ATILE,
                   acc, wm, wn, a_lrow, a_c8, b_lrow, b_c8);
        }

        // ---- epilogue: + bias, convert fp16, write fs (cols<256) or fd ----
        {
            int col0 = blk * 128;
            __half* Cb = (col0 < 256) ? g_fsh : g_fdh;
            const int cb0 = (col0 < 256) ? col0 : col0 - 256;
#pragma unroll
            for (int nt = 0; nt < 8; nt++) {
                int gcol = col0 + wn + nt * 8 + (lane & 3) * 2;
                float b0 = g_bias2[gcol], b1 = g_bias2[gcol + 1];
                int cc = cb0 + wn + nt * 8 + (lane & 3) * 2;
#pragma unroll
                for (int mt = 0; mt < 2; mt++) {
                    int rr = row0 + wm + mt * 16 + (lane >> 2);
                    if (rr < NN)
                        *(__half2*)&Cb[(size_t)rr * HD + cc] =
                            __floats2half2_rn(acc[mt][nt][0] + b0, acc[mt][nt][1] + b1);
                    if (rr + 8 < NN)
                        *(__half2*)&Cb[(size_t)(rr + 8) * HD + cc] =
                            __floats2half2_rn(acc[mt][nt][2] + b0, acc[mt][nt][3] + b1);
                }
            }
        }

        if (blk < 3) {
            CPA_WAIT0();
            __syncthreads();
        }
    }
}

// ---------------- edge aggregation: one warp per node, 4-edge batches ---------
__global__ void __launch_bounds__(256) k_agg(const float* __restrict__ attn, int last) {
    int gw = (blockIdx.x * blockDim.x + threadIdx.x) >> 5;
    int lane = threadIdx.x & 31;
    if (gw >= NN) return;

    int base = lane * 8;
    float fd[8], at[8];
    {
        uint4 u = *(const uint4*)(g_fdh + (size_t)gw * HD + base);
        unp8(u, fd);
        float4 atA = *(const float4*)(attn + base);
        float4 atB = *(const float4*)(attn + base + 4);
        at[0] = atA.x; at[1] = atA.y; at[2] = atA.z; at[3] = atA.w;
        at[4] = atB.x; at[5] = atB.y; at[6] = atB.z; at[7] = atB.w;
    }

    float m = -1e30f, denom = 0.f;
    float acc[8];
#pragma unroll
    for (int j = 0; j < 8; j++) acc[j] = 0.f;

    int e0 = g_rowoff[gw], e1 = g_rowoff[gw + 1];
    for (int e = e0; e < e1; e += 4) {
        int n = e1 - e;   // >= 1
        int s0 = g_esrc[e];
        int s1 = (n > 1) ? g_esrc[e + 1] : s0;
        int s2 = (n > 2) ? g_esrc[e + 2] : s0;
        int s3 = (n > 3) ? g_esrc[e + 3] : s0;
        uint4 u0 = *(const uint4*)(g_fsh + (size_t)s0 * HD + base);
        uint4 u1 = *(const uint4*)(g_fsh + (size_t)s1 * HD + base);
        uint4 u2 = *(const uint4*)(g_fsh + (size_t)s2 * HD + base);
        uint4 u3 = *(const uint4*)(g_fsh + (size_t)s3 * HD + base);

        float f0[8], f1[8], f2[8], f3[8];
        unp8(u0, f0); unp8(u1, f1); unp8(u2, f2); unp8(u3, f3);

        float p0 = 0.f, p1 = 0.f, p2 = 0.f, p3 = 0.f;
#pragma unroll
        for (int j = 0; j < 8; j++) {
            float v;
            v = f0[j] + fd[j]; v = (v > 0.f) ? v : 0.2f * v; p0 = fmaf(v, at[j], p0);
            v = f1[j] + fd[j]; v = (v > 0.f) ? v : 0.2f * v; p1 = fmaf(v, at[j], p1);
            v = f2[j] + fd[j]; v = (v > 0.f) ? v : 0.2f * v; p2 = fmaf(v, at[j], p2);
            v = f3[j] + fd[j]; v = (v > 0.f) ? v : 0.2f * v; p3 = fmaf(v, at[j], p3);
        }
#pragma unroll
        for (int off = 1; off < 8; off <<= 1) {
            p0 += __shfl_xor_sync(0xffffffffu, p0, off);
            p1 += __shfl_xor_sync(0xffffffffu, p1, off);
            p2 += __shfl_xor_sync(0xffffffffu, p2, off);
            p3 += __shfl_xor_sync(0xffffffffu, p3, off);
        }
        if (n < 2) p1 = -1e30f;
        if (n < 3) p2 = -1e30f;
        if (n < 4) p3 = -1e30f;

        float mb = fmaxf(fmaxf(p0, p1), fmaxf(p2, p3));
        float nm = fmaxf(m, mb);
        float sc = __expf(m - nm);
        float w0 = __expf(p0 - nm);
        float w1 = __expf(p1 - nm);
        float w2 = __expf(p2 - nm);
        float w3 = __expf(p3 - nm);
        m = nm;
        denom = fmaf(denom, sc, (w0 + w1) + (w2 + w3));
#pragma unroll
        for (int j = 0; j < 8; j++) {
            float s = fmaf(w0, f0[j], w1 * f1[j]);
            s = fmaf(w2, f2[j], s);
            s = fmaf(w3, f3[j], s);
            acc[j] = fmaf(acc[j], sc, s);
        }
    }

    float inv = (denom > 0.f) ? (1.f / denom) : 0.f;
    float t[8];
#pragma unroll
    for (int j = 0; j < 8; j++) t[j] = tanhf(acc[j] * inv);
#pragma unroll
    for (int j = 0; j < 8; j++) {
        t[j] += __shfl_xor_sync(0xffffffffu, t[j], 8);
        t[j] += __shfl_xor_sync(0xffffffffu, t[j], 16);
    }
    if (lane < 8) {
        size_t ofs = (size_t)gw * 64 + lane * 8;
        if (last) {
            float* hout = g_hfin + ofs;
#pragma unroll
            for (int j = 0; j < 8; j++) hout[j] = t[j];
        } else {
            __nv_bfloat16* ah = g_Ahi + ofs;
            __nv_bfloat16* al = g_Alo + ofs;
#pragma unroll
            for (int j = 0; j < 8; j++) {
                __nv_bfloat16 hi = __float2bfloat16(t[j]);
                ah[j] = hi;
                al[j] = __float2bfloat16(t[j] - __bfloat162float(hi));
            }
        }
    }
}

// ---------------- graph pooling + output head --------------------------------
__global__ void k_pool(const float* __restrict__ is_root, const int* __restrict__ gid) {
    __shared__ float sh[BG * 64];
    int t = threadIdx.x;
    for (int x = t; x < BG * 64; x += 256) sh[x] = 0.f;
    __syncthreads();
    for (int idx = blockIdx.x * 256 + t; idx < NN * 64; idx += gridDim.x * 256) {
        int i = idx >> 6, d = idx & 63;
        atomicAdd(&sh[(gid[i] << 6) | d], g_hfin[idx] * is_root[i]);
    }
    __syncthreads();
    for (int x = t; x < BG * 64; x += 256) atomicAdd(&g_hg[x], sh[x]);
}

__global__ void k_out(const float* __restrict__ W_out, const float* __restrict__ b_out,
                      float* __restrict__ out) {
    int t = threadIdx.x;
    if (t >= BG * 32) return;
    int b = t >> 5, j = t & 31;
    float s = b_out[j];
#pragma unroll
    for (int d = 0; d < 64; d++) s = fmaf(g_hg[b * 64 + d], W_out[d * 32 + j], s);
    out[t] = s;
}

// ---------------- launcher ----------------------------------------------------
extern "C" void kernel_launch(void* const* d_in, const int* in_sizes, int n_in,
                              void* d_out, int out_size) {
    const float* feat    = (const float*)d_in[0];
    const float* is_root = (const float*)d_in[1];
    const int*   src     = (const int*)  d_in[2];
    const int*   dst     = (const int*)  d_in[3];
    const int*   gid     = (const int*)  d_in[4];
    const float* W_in    = (const float*)d_in[5];
    const float* b_in    = (const float*)d_in[6];
    const float* W_src   = (const float*)d_in[7];
    const float* b_src   = (const float*)d_in[8];
    const float* W_dst   = (const float*)d_in[9];
    const float* b_dst   = (const float*)d_in[10];
    const float* attn    = (const float*)d_in[11];
    const float* W_out   = (const float*)d_in[12];
    const float* b_out   = (const float*)d_in[13];
    float* out = (float*)d_out;

    cudaFuncSetAttribute(k_mma, cudaFuncAttributeMaxDynamicSharedMemorySize, SMEM_TOT);

    k_cvtW<<<NBLK, 256>>>(W_src, W_dst, b_src, b_dst);
    k_h0<<<(NN * 64 + 255) / 256, 256>>>(feat, W_in, b_in, dst);
    k_scan1<<<NBLK, 256>>>();
    k_scan3<<<NBLK, 256>>>();
    k_scatter<<<(EE + 255) / 256, 256>>>(src, dst);

    const int nrb = (NN + 127) / 128;   // 391 row blocks
    for (int L = 0; L < 4; L++) {
        k_mma<<<nrb, 256, SMEM_TOT>>>(L == 0 ? 0 : 1);
        k_agg<<<(NN * 32 + 255) / 256, 256>>>(attn, L == 3 ? 1 : 0);
    }

    k_pool<<<200, 256>>>(is_root, gid);
    k_out<<<1, 512>>>(W_out, b_out, out);
}